// round 10
// baseline (speedup 1.0000x reference)
#include <cuda_runtime.h>
#include <cuda_bf16.h>
#include <mma.h>
#include <math.h>

using namespace nvcuda;

#define N_NODES_C 20000
#define N_EDGES_C 320000
#define NH 128
#define DIN 262
#define NLAYERS 3
#define BN_EPS 1e-5f
#define GRID_P 148

// ---------------- scratch ----------------
__device__ float g_x[N_NODES_C * NH];
__device__ float g_x2[N_NODES_C * NH];
__device__ float g_Y[(size_t)N_NODES_C * 256];              // [Y1 | Y2] per node
__device__ __nv_bfloat16 g_h[(size_t)N_EDGES_C * NH];       // hpre (bf16, 82 MB)
__device__ float g_s[N_EDGES_C];
__device__ float g_stats[2 * NH];
__device__ float g_bnA[NH];
__device__ float g_bnB[NH];
__device__ int   g_cnt[N_NODES_C];
__device__ int   g_rowptr[N_NODES_C + 1];
__device__ int   g_eidx[N_EDGES_C];

__device__ __forceinline__ float psi_f(float z) {
    return copysignf(log1pf(fabsf(z)), z);
}
__device__ __forceinline__ float sigmoid_f(float z) {
    return 1.0f / (1.0f + expf(-z));
}
__device__ __forceinline__ __nv_bfloat16 bf(float x) { return __float2bfloat16(x); }

typedef wmma::fragment<wmma::matrix_a, 16, 16, 16, __nv_bfloat16, wmma::row_major> FragA;
typedef wmma::fragment<wmma::matrix_b, 16, 16, 16, __nv_bfloat16, wmma::row_major> FragB;
typedef wmma::fragment<wmma::accumulator, 16, 16, 16, float> FragC;

// ================= CSR build ==========================================================
__global__ void k_hist(const int* __restrict__ ei) {
    int e = blockIdx.x * 256 + threadIdx.x;
    if (e < N_EDGES_C) atomicAdd(&g_cnt[ei[e]], 1);
}

__global__ void k_scan() {
    __shared__ int part[1024];
    int t = threadIdx.x;
    int base = t * 20;
    int s = 0;
    for (int i = 0; i < 20; i++) {
        int idx = base + i;
        if (idx < N_NODES_C) s += g_cnt[idx];
    }
    part[t] = s;
    __syncthreads();
    for (int off = 1; off < 1024; off <<= 1) {
        int v = (t >= off) ? part[t - off] : 0;
        __syncthreads();
        part[t] += v;
        __syncthreads();
    }
    int run = (t == 0) ? 0 : part[t - 1];
    for (int i = 0; i < 20; i++) {
        int idx = base + i;
        if (idx <= N_NODES_C) g_rowptr[idx] = run;
        if (idx < N_NODES_C) run += g_cnt[idx];
    }
    for (int i = 0; i < 20; i++) {
        int idx = base + i;
        if (idx < N_NODES_C) g_cnt[idx] = 0;
    }
}

__global__ void k_fillcsr(const int* __restrict__ ei) {
    int e = blockIdx.x * 256 + threadIdx.x;
    if (e < N_EDGES_C) {
        int r = ei[e];
        int slot = g_rowptr[r] + atomicAdd(&g_cnt[r], 1);
        g_eidx[slot] = e;
    }
}

__global__ void k_sortseg() {
    int n = blockIdx.x * 256 + threadIdx.x;
    if (n >= N_NODES_C) return;
    int beg = g_rowptr[n], end = g_rowptr[n + 1];
    for (int i = beg + 1; i < end; i++) {
        int v = g_eidx[i], j = i - 1;
        while (j >= beg && g_eidx[j] > v) { g_eidx[j + 1] = g_eidx[j]; j--; }
        g_eidx[j + 1] = v;
    }
}

// ================= node GEMM: Y = X @ [W1a | W1b] (2 CTAs/SM) =========================
__global__ void __launch_bounds__(256, 2)
k_node(const float* __restrict__ xin, const float* __restrict__ W1) {
    extern __shared__ __align__(16) char smraw[];
    __nv_bfloat16* Bs = (__nv_bfloat16*)smraw;        // 128 x 264
    __nv_bfloat16* As = Bs + 128 * 264;               // 64 x 136

    int tid = threadIdx.x;
    int warp = tid >> 5;
    int wy = warp >> 2, wx = warp & 3;

    for (int idx = tid; idx < 128 * 256; idx += 256) {
        int k = idx >> 8, c = idx & 255;
        float v = (c < 128) ? W1[(size_t)k * NH + c] : W1[(size_t)(128 + k) * NH + (c - 128)];
        Bs[k * 264 + c] = bf(v);
    }

    const int NT = (N_NODES_C + 63) / 64;   // 313
    for (int tile = blockIdx.x; tile < NT; tile += GRID_P * 2) {
        int n0 = tile * 64;
        __syncthreads();
        for (int idx = tid; idx < 64 * 32; idx += 256) {
            int e = idx >> 5, g = idx & 31;
            int r = n0 + e; if (r >= N_NODES_C) r = N_NODES_C - 1;
            float4 v = *(const float4*)&xin[(size_t)r * NH + g * 4];
            __nv_bfloat16* dst = &As[e * 136 + g * 4];
            dst[0] = bf(v.x); dst[1] = bf(v.y); dst[2] = bf(v.z); dst[3] = bf(v.w);
        }
        __syncthreads();

        FragC acc[2][4];
#pragma unroll
        for (int i = 0; i < 2; i++)
#pragma unroll
            for (int j = 0; j < 4; j++) wmma::fill_fragment(acc[i][j], 0.f);

#pragma unroll
        for (int kk = 0; kk < NH; kk += 16) {
            FragA a0, a1;
            wmma::load_matrix_sync(a0, &As[(wy * 32) * 136 + kk], 136);
            wmma::load_matrix_sync(a1, &As[(wy * 32 + 16) * 136 + kk], 136);
#pragma unroll
            for (int j = 0; j < 4; j++) {
                FragB bfr;
                wmma::load_matrix_sync(bfr, &Bs[kk * 264 + wx * 64 + j * 16], 264);
                wmma::mma_sync(acc[0][j], a0, bfr, acc[0][j]);
                wmma::mma_sync(acc[1][j], a1, bfr, acc[1][j]);
            }
        }
#pragma unroll
        for (int i = 0; i < 2; i++) {
            int row0 = n0 + wy * 32 + i * 16;
            if (row0 + 16 <= N_NODES_C) {
#pragma unroll
                for (int j = 0; j < 4; j++)
                    wmma::store_matrix_sync(&g_Y[(size_t)row0 * 256 + wx * 64 + j * 16],
                                            acc[i][j], 256, wmma::mem_row_major);
            }
        }
    }
}

// ================= stats pass: norms/dots + hpre (bf16 store) + BN sums ===============
__global__ void __launch_bounds__(256)
k_stats(const float* __restrict__ xin, const int* __restrict__ ei,
        const float* __restrict__ ea, const float* __restrict__ W1c) {
    __shared__ float w1c[6 * 128];
    __shared__ float red[2 * 128];

    int tid = threadIdx.x;
    int warp = tid >> 5, lane = tid & 31;
    for (int i = tid; i < 6 * 128; i += 256) w1c[i] = W1c[i];
    if (tid < 256) red[tid] = 0.f;
    __syncthreads();

    float acc_s[4] = {0.f, 0.f, 0.f, 0.f};
    float acc_q[4] = {0.f, 0.f, 0.f, 0.f};
    int col = lane * 4;
    float sgn0 = (lane == 0) ? 1.f : -1.f;

    int gw = blockIdx.x * 8 + warp;
    int tw = gridDim.x * 8;
    for (int e = gw; e < N_EDGES_C; e += tw) {
        int r = ei[e];
        int c = ei[N_EDGES_C + e];
        float4 xr = *(const float4*)&xin[(size_t)r * NH + col];
        float4 xc = *(const float4*)&xin[(size_t)c * NH + col];
        float dx = xr.x - xc.x, dy = xr.y - xc.y, dz = xr.z - xc.z, dw = xr.w - xc.w;
        float dd = sgn0 * dx * dx - dy * dy - dz * dz - dw * dw;
        float ij = sgn0 * xr.x * xc.x - xr.y * xc.y - xr.z * xc.z - xr.w * xc.w;
#pragma unroll
        for (int o = 16; o; o >>= 1) {
            dd += __shfl_xor_sync(0xffffffffu, dd, o);
            ij += __shfl_xor_sync(0xffffffffu, ij, o);
        }
        float nrm = psi_f(dd), dt = psi_f(ij);

        float4 y1 = *(const float4*)&g_Y[(size_t)r * 256 + col];
        float4 y2 = *(const float4*)&g_Y[(size_t)c * 256 + 128 + col];
        float4 eav = *(const float4*)&ea[(size_t)e * 4];
        float hv[4] = {y1.x + y2.x, y1.y + y2.y, y1.z + y2.z, y1.w + y2.w};
        float ho[4];
#pragma unroll
        for (int j = 0; j < 4; j++) {
            int cc = col + j;
            float h = hv[j];
            h = fmaf(eav.x, w1c[cc], h);
            h = fmaf(eav.y, w1c[128 + cc], h);
            h = fmaf(eav.z, w1c[256 + cc], h);
            h = fmaf(eav.w, w1c[384 + cc], h);
            h = fmaf(nrm, w1c[512 + cc], h);
            h = fmaf(dt, w1c[640 + cc], h);
            ho[j] = h;
            acc_s[j] += h;
            acc_q[j] = fmaf(h, h, acc_q[j]);
        }
        __nv_bfloat162 h01 = __floats2bfloat162_rn(ho[0], ho[1]);
        __nv_bfloat162 h23 = __floats2bfloat162_rn(ho[2], ho[3]);
        uint2 pk;
        pk.x = *(unsigned int*)&h01;
        pk.y = *(unsigned int*)&h23;
        *(uint2*)&g_h[(size_t)e * NH + col] = pk;
    }
#pragma unroll
    for (int j = 0; j < 4; j++) {
        atomicAdd(&red[col + j], acc_s[j]);
        atomicAdd(&red[128 + col + j], acc_q[j]);
    }
    __syncthreads();
    if (tid < 256) atomicAdd(&g_stats[tid], red[tid]);
}

// ================= BN finalize =========================================================
__global__ void k_bnfin(const float* __restrict__ gamma, const float* __restrict__ beta) {
    int c = threadIdx.x;
    float inv = 1.f / (float)N_EDGES_C;
    float mean = g_stats[c] * inv;
    float var = g_stats[NH + c] * inv - mean * mean;
    float sc = gamma[c] * rsqrtf(var + BN_EPS);
    g_bnA[c] = sc;
    g_bnB[c] = beta[c] - mean * sc;
    g_stats[c] = 0.f;
    g_stats[NH + c] = 0.f;
}

// ================= fused edge MLP: FOUR 4-warp pipelines per CTA ======================
// 512 threads = 4 groups x 4 warps. Each group: 32-edge tile, warps split 128 cols.
// Every SMSP holds one warp of each group -> 4-way phase diversity.
#define BARG() asm volatile("bar.sync %0, 128;" :: "r"(group + 1) : "memory")

__global__ void __launch_bounds__(512, 1)
k_fused(const float* __restrict__ W2, const float* __restrict__ b2,
        const float* __restrict__ Wa, const float* __restrict__ ba,
        const float* __restrict__ Wb,
        const float* __restrict__ Wm, const float* __restrict__ bm) {
    extern __shared__ __align__(16) char smraw[];
    __nv_bfloat16* W2s = (__nv_bfloat16*)smraw;       // 128 x 136
    __nv_bfloat16* Was = W2s + 128 * 136;             // 128 x 136
    __nv_bfloat16* Sall = Was + 128 * 136;            // 4 x (32 x 136) bf16
    float* Sfall = (float*)(Sall + 4 * 32 * 136);     // 4 x (32 x 132) fp32
    float* p_bnA = Sfall + 4 * 32 * 132;
    float* p_bnB = p_bnA + NH;
    float* p_b2  = p_bnB + NH;
    float* p_ba  = p_b2 + NH;
    float* p_Wm  = p_ba + NH;
    float* p_Wb  = p_Wm + NH;
    float* wg_all = p_Wb + NH;                        // 4 x 32

    int tid = threadIdx.x;
    int warp = tid >> 5, lane = tid & 31;
    int group = warp >> 2;                 // 0..3
    int gwarp = warp & 3;                  // 0..3 (column quarter)
    float bmv = bm[0];

    __nv_bfloat16* S  = Sall + group * 32 * 136;
    float*         Sf = Sfall + group * 32 * 132;
    float*         wgv = wg_all + group * 32;

    for (int idx = tid; idx < NH * NH; idx += 512) {
        int k = idx >> 7, c = idx & 127;
        W2s[k * 136 + c] = bf(W2[idx]);
        Was[k * 136 + c] = bf(Wa[idx]);
    }
    if (tid < NH) {
        p_bnA[tid] = g_bnA[tid];
        p_bnB[tid] = g_bnB[tid];
        p_b2[tid]  = b2[tid];
        p_ba[tid]  = ba[tid];
        p_Wm[tid]  = Wm[tid];
        p_Wb[tid]  = Wb[tid];
    }
    __syncthreads();

    const int NT = N_EDGES_C / 32;          // 10000
    int tid_g = tid & 127;

    for (int tile = blockIdx.x * 4 + group; tile < NT; tile += GRID_P * 4) {
        int e0 = tile * 32;

        // phase 1: sequential bf16 hpre stream; BN + ReLU -> S (packed uint4 stores)
        for (int idx = tid_g; idx < 32 * 16; idx += 128) {
            int e = idx >> 4, g = idx & 15;
            uint4 u = *(const uint4*)&g_h[(size_t)(e0 + e) * NH + g * 8];
            __nv_bfloat162* hp = (__nv_bfloat162*)&u;
            int cc0 = g * 8;
            uint4 outp;
            __nv_bfloat162* op = (__nv_bfloat162*)&outp;
#pragma unroll
            for (int q = 0; q < 4; q++) {
                float2 f = __bfloat1622float2(hp[q]);
                int c0 = cc0 + q * 2;
                float v0 = fmaxf(fmaf(f.x, p_bnA[c0 + 0], p_bnB[c0 + 0]), 0.f);
                float v1 = fmaxf(fmaf(f.y, p_bnA[c0 + 1], p_bnB[c0 + 1]), 0.f);
                op[q] = __floats2bfloat162_rn(v0, v1);
            }
            *(uint4*)&S[e * 136 + g * 8] = outp;
        }
        BARG();

        // phase 2: Sf = S @ W2   (warp: rows 0-31, cols gwarp*32..+32)
        {
            FragC acc[2][2];
#pragma unroll
            for (int i = 0; i < 2; i++)
#pragma unroll
                for (int j = 0; j < 2; j++) wmma::fill_fragment(acc[i][j], 0.f);
#pragma unroll
            for (int kk = 0; kk < NH; kk += 16) {
                FragA a0, a1; FragB b0, b1;
                wmma::load_matrix_sync(a0, &S[0 * 136 + kk], 136);
                wmma::load_matrix_sync(a1, &S[16 * 136 + kk], 136);
                wmma::load_matrix_sync(b0, &W2s[kk * 136 + gwarp * 32], 136);
                wmma::load_matrix_sync(b1, &W2s[kk * 136 + gwarp * 32 + 16], 136);
                wmma::mma_sync(acc[0][0], a0, b0, acc[0][0]);
                wmma::mma_sync(acc[0][1], a0, b1, acc[0][1]);
                wmma::mma_sync(acc[1][0], a1, b0, acc[1][0]);
                wmma::mma_sync(acc[1][1], a1, b1, acc[1][1]);
            }
#pragma unroll
            for (int i = 0; i < 2; i++)
#pragma unroll
                for (int j = 0; j < 2; j++)
                    wmma::store_matrix_sync(&Sf[(i * 16) * 132 + gwarp * 32 + j * 16],
                                            acc[i][j], 132, wmma::mem_row_major);
        }
        BARG();

        // phase 3: bias + ReLU -> S; gate -> wgv  (warp: 8 edges)
#pragma unroll
        for (int t = 0; t < 8; t++) {
            int e = gwarp * 8 + t;
            float v[4];
            float p = 0.f;
#pragma unroll
            for (int u = 0; u < 4; u++) {
                int c = lane + 32 * u;
                v[u] = fmaxf(Sf[e * 132 + c] + p_b2[c], 0.f);
                p = fmaf(v[u], p_Wm[c], p);
            }
#pragma unroll
            for (int o = 16; o; o >>= 1) p += __shfl_xor_sync(0xffffffffu, p, o);
            if (lane == 0) wgv[e] = sigmoid_f(p + bmv);
#pragma unroll
            for (int u = 0; u < 4; u++) {
                int c = lane + 32 * u;
                S[e * 136 + c] = bf(v[u]);
            }
        }
        BARG();

        // phase 4: Sf = S @ Wa
        {
            FragC acc[2][2];
#pragma unroll
            for (int i = 0; i < 2; i++)
#pragma unroll
                for (int j = 0; j < 2; j++) wmma::fill_fragment(acc[i][j], 0.f);
#pragma unroll
            for (int kk = 0; kk < NH; kk += 16) {
                FragA a0, a1; FragB b0, b1;
                wmma::load_matrix_sync(a0, &S[0 * 136 + kk], 136);
                wmma::load_matrix_sync(a1, &S[16 * 136 + kk], 136);
                wmma::load_matrix_sync(b0, &Was[kk * 136 + gwarp * 32], 136);
                wmma::load_matrix_sync(b1, &Was[kk * 136 + gwarp * 32 + 16], 136);
                wmma::mma_sync(acc[0][0], a0, b0, acc[0][0]);
                wmma::mma_sync(acc[0][1], a0, b1, acc[0][1]);
                wmma::mma_sync(acc[1][0], a1, b0, acc[1][0]);
                wmma::mma_sync(acc[1][1], a1, b1, acc[1][1]);
            }
#pragma unroll
            for (int i = 0; i < 2; i++)
#pragma unroll
                for (int j = 0; j < 2; j++)
                    wmma::store_matrix_sync(&Sf[(i * 16) * 132 + gwarp * 32 + j * 16],
                                            acc[i][j], 132, wmma::mem_row_major);
        }
        BARG();

        // phase 5: s = ReLU(wg * Sf + ba) . Wb -> g_s
#pragma unroll
        for (int t = 0; t < 8; t++) {
            int e = gwarp * 8 + t;
            float wg = wgv[e];
            float p = 0.f;
#pragma unroll
            for (int u = 0; u < 4; u++) {
                int c = lane + 32 * u;
                p = fmaf(fmaxf(fmaf(wg, Sf[e * 132 + c], p_ba[c]), 0.f), p_Wb[c], p);
            }
#pragma unroll
            for (int o = 16; o; o >>= 1) p += __shfl_xor_sync(0xffffffffu, p, o);
            if (lane == 0) g_s[e0 + e] = p;
        }
        BARG();
    }
}

// ================= aggregation (+ fused head on final layer) ==========================
__global__ void __launch_bounds__(256)
k_agg(const float* __restrict__ xin, float* __restrict__ xout,
      const int* __restrict__ ei, int is_final,
      const float* __restrict__ We, const float* __restrict__ be,
      float* __restrict__ out) {
    int n = blockIdx.x * 8 + (threadIdx.x >> 5);
    if (n >= N_NODES_C) return;
    int lane = threadIdx.x & 31;
    float4 xi = *(const float4*)&xin[(size_t)n * NH + lane * 4];
    float4 acc = xi;
    int beg = g_rowptr[n], end = g_rowptr[n + 1];
    for (int j = beg; j < end; j++) {
        int e = g_eidx[j];
        float s = g_s[e];
        int c = ei[N_EDGES_C + e];
        float4 xc = *(const float4*)&xin[(size_t)c * NH + lane * 4];
        acc.x += fminf(fmaxf((xi.x - xc.x) * s, -100.f), 100.f);
        acc.y += fminf(fmaxf((xi.y - xc.y) * s, -100.f), 100.f);
        acc.z += fminf(fmaxf((xi.z - xc.z) * s, -100.f), 100.f);
        acc.w += fminf(fmaxf((xi.w - xc.w) * s, -100.f), 100.f);
    }
    if (is_final) {
        int k0 = lane * 4;
        float p0 = acc.x * We[k0 * 2] + acc.y * We[(k0 + 1) * 2]
                 + acc.z * We[(k0 + 2) * 2] + acc.w * We[(k0 + 3) * 2];
        float p1 = acc.x * We[k0 * 2 + 1] + acc.y * We[(k0 + 1) * 2 + 1]
                 + acc.z * We[(k0 + 2) * 2 + 1] + acc.w * We[(k0 + 3) * 2 + 1];
#pragma unroll
        for (int o = 16; o; o >>= 1) {
            p0 += __shfl_xor_sync(0xffffffffu, p0, o);
            p1 += __shfl_xor_sync(0xffffffffu, p1, o);
        }
        if (lane == 0) {
            out[(size_t)n * 2 + 0] = sigmoid_f(p0 + be[0]);
            out[(size_t)n * 2 + 1] = sigmoid_f(p1 + be[1]);
        }
    } else {
        *(float4*)&xout[(size_t)n * NH + lane * 4] = acc;
    }
}

// ================= launch ==============================================================
extern "C" void kernel_launch(void* const* d_in, const int* in_sizes, int n_in,
                              void* d_out, int out_size) {
    (void)in_sizes; (void)n_in; (void)out_size;
    const float* x     = (const float*)d_in[0];
    const int*   ei    = (const int*)d_in[1];
    const float* ea    = (const float*)d_in[2];
    const float* W1    = (const float*)d_in[3];
    const float* gamma = (const float*)d_in[4];
    const float* beta  = (const float*)d_in[5];
    const float* W2    = (const float*)d_in[6];
    const float* b2    = (const float*)d_in[7];
    const float* Wa    = (const float*)d_in[8];
    const float* ba    = (const float*)d_in[9];
    const float* Wb    = (const float*)d_in[10];
    const float* Wm    = (const float*)d_in[11];
    const float* bm    = (const float*)d_in[12];
    const float* We    = (const float*)d_in[13];
    const float* be    = (const float*)d_in[14];
    float* out = (float*)d_out;

    const int smem_node  = 128 * 264 * 2 + 64 * 136 * 2;
    const int smem_fused = 2 * 128 * 136 * 2          // W2s, Was
                         + 4 * 32 * 136 * 2           // S x4 groups
                         + 4 * 32 * 132 * 4           // Sf x4 groups
                         + (6 * 128 + 128) * 4;
    cudaFuncSetAttribute(k_node,  cudaFuncAttributeMaxDynamicSharedMemorySize, smem_node);
    cudaFuncSetAttribute(k_fused, cudaFuncAttributeMaxDynamicSharedMemorySize, smem_fused);

    void *px = nullptr, *pcnt = nullptr, *pstats = nullptr, *px2 = nullptr;
    cudaGetSymbolAddress(&px, g_x);
    cudaGetSymbolAddress(&px2, g_x2);
    cudaGetSymbolAddress(&pcnt, g_cnt);
    cudaGetSymbolAddress(&pstats, g_stats);

    cudaMemcpyAsync(px, x, sizeof(float) * N_NODES_C * NH, cudaMemcpyDeviceToDevice, 0);
    cudaMemsetAsync(pcnt, 0, N_NODES_C * sizeof(int), 0);
    cudaMemsetAsync(pstats, 0, 2 * NH * sizeof(float), 0);

    k_hist<<<(N_EDGES_C + 255) / 256, 256>>>(ei);
    k_scan<<<1, 1024>>>();
    k_fillcsr<<<(N_EDGES_C + 255) / 256, 256>>>(ei);
    k_sortseg<<<(N_NODES_C + 255) / 256, 256>>>();

    float* bufA = (float*)px;
    float* bufB = (float*)px2;

    for (int l = 0; l < NLAYERS; l++) {
        const float* W1l = W1 + (size_t)l * DIN * NH;
        const float* xin  = (l & 1) ? bufB : bufA;
        float*       xout = (l & 1) ? bufA : bufB;
        int is_final = (l == NLAYERS - 1);
        k_node<<<GRID_P * 2, 256, smem_node>>>(xin, W1l);
        k_stats<<<1184, 256>>>(xin, ei, ea, W1l + 256 * NH);
        k_bnfin<<<1, 128>>>(gamma + l * NH, beta + l * NH);
        k_fused<<<GRID_P, 512, smem_fused>>>(W2 + (size_t)l * NH * NH, b2 + l * NH,
                                             Wa + (size_t)l * NH * NH, ba + l * NH,
                                             Wb + l * NH,
                                             Wm + l * NH, bm + l);
        k_agg<<<(N_NODES_C + 7) / 8, 256>>>(xin, xout, ei, is_final, We, be, out);
    }
}

// round 11
// speedup vs baseline: 1.0150x; 1.0150x over previous
#include <cuda_runtime.h>
#include <cuda_bf16.h>
#include <mma.h>
#include <math.h>

using namespace nvcuda;

#define N_NODES_C 20000
#define N_EDGES_C 320000
#define NH 128
#define DIN 262
#define NLAYERS 3
#define BN_EPS 1e-5f
#define GRID_P 148

// ---------------- scratch ----------------
__device__ float g_x[N_NODES_C * NH];
__device__ float g_x2[N_NODES_C * NH];
__device__ float g_Y[(size_t)N_NODES_C * 256];              // [Y1 | Y2] per node
__device__ __nv_bfloat16 g_h[(size_t)N_EDGES_C * NH];       // hpre (bf16, slot order)
__device__ float g_s[N_EDGES_C];                            // per-slot phi_x scalar
__device__ float g_eap[N_EDGES_C * 4];                      // permuted edge_attr
__device__ int   g_colj[N_EDGES_C];                         // permuted col index
__device__ float g_stats[2 * NH];
__device__ float g_bnA[NH];
__device__ float g_bnB[NH];
__device__ int   g_cnt[N_NODES_C];
__device__ int   g_rowptr[N_NODES_C + 1];
__device__ int   g_eidx[N_EDGES_C];

__device__ __forceinline__ float psi_f(float z) {
    return copysignf(log1pf(fabsf(z)), z);
}
__device__ __forceinline__ float sigmoid_f(float z) {
    return 1.0f / (1.0f + expf(-z));
}
__device__ __forceinline__ __nv_bfloat16 bf(float x) { return __float2bfloat16(x); }

typedef wmma::fragment<wmma::matrix_a, 16, 16, 16, __nv_bfloat16, wmma::row_major> FragA;
typedef wmma::fragment<wmma::matrix_b, 16, 16, 16, __nv_bfloat16, wmma::row_major> FragB;
typedef wmma::fragment<wmma::accumulator, 16, 16, 16, float> FragC;

// ================= CSR build (once per launch) ========================================
__global__ void k_hist(const int* __restrict__ ei) {
    int e = blockIdx.x * 256 + threadIdx.x;
    if (e < N_EDGES_C) atomicAdd(&g_cnt[ei[e]], 1);
}

__global__ void k_scan() {
    __shared__ int part[1024];
    int t = threadIdx.x;
    int base = t * 20;
    int s = 0;
    for (int i = 0; i < 20; i++) {
        int idx = base + i;
        if (idx < N_NODES_C) s += g_cnt[idx];
    }
    part[t] = s;
    __syncthreads();
    for (int off = 1; off < 1024; off <<= 1) {
        int v = (t >= off) ? part[t - off] : 0;
        __syncthreads();
        part[t] += v;
        __syncthreads();
    }
    int run = (t == 0) ? 0 : part[t - 1];
    for (int i = 0; i < 20; i++) {
        int idx = base + i;
        if (idx <= N_NODES_C) g_rowptr[idx] = run;
        if (idx < N_NODES_C) run += g_cnt[idx];
    }
    for (int i = 0; i < 20; i++) {
        int idx = base + i;
        if (idx < N_NODES_C) g_cnt[idx] = 0;
    }
}

__global__ void k_fillcsr(const int* __restrict__ ei) {
    int e = blockIdx.x * 256 + threadIdx.x;
    if (e < N_EDGES_C) {
        int r = ei[e];
        int slot = g_rowptr[r] + atomicAdd(&g_cnt[r], 1);
        g_eidx[slot] = e;
    }
}

__global__ void k_sortseg() {
    int n = blockIdx.x * 256 + threadIdx.x;
    if (n >= N_NODES_C) return;
    int beg = g_rowptr[n], end = g_rowptr[n + 1];
    for (int i = beg + 1; i < end; i++) {
        int v = g_eidx[i], j = i - 1;
        while (j >= beg && g_eidx[j] > v) { g_eidx[j + 1] = g_eidx[j]; j--; }
        g_eidx[j + 1] = v;
    }
}

// permuted col-index and edge_attr in slot order
__global__ void k_perm(const int* __restrict__ ei, const float* __restrict__ ea) {
    int j = blockIdx.x * 256 + threadIdx.x;
    if (j < N_EDGES_C) {
        int e = g_eidx[j];
        g_colj[j] = ei[N_EDGES_C + e];
        *(float4*)&g_eap[(size_t)j * 4] = *(const float4*)&ea[(size_t)e * 4];
    }
}

// ================= node GEMM: Y = X @ [W1a | W1b] (2 CTAs/SM) =========================
__global__ void __launch_bounds__(256, 2)
k_node(const float* __restrict__ xin, const float* __restrict__ W1) {
    extern __shared__ __align__(16) char smraw[];
    __nv_bfloat16* Bs = (__nv_bfloat16*)smraw;        // 128 x 264
    __nv_bfloat16* As = Bs + 128 * 264;               // 64 x 136

    int tid = threadIdx.x;
    int warp = tid >> 5;
    int wy = warp >> 2, wx = warp & 3;

    for (int idx = tid; idx < 128 * 256; idx += 256) {
        int k = idx >> 8, c = idx & 255;
        float v = (c < 128) ? W1[(size_t)k * NH + c] : W1[(size_t)(128 + k) * NH + (c - 128)];
        Bs[k * 264 + c] = bf(v);
    }

    const int NT = (N_NODES_C + 63) / 64;   // 313
    for (int tile = blockIdx.x; tile < NT; tile += GRID_P * 2) {
        int n0 = tile * 64;
        __syncthreads();
        for (int idx = tid; idx < 64 * 32; idx += 256) {
            int e = idx >> 5, g = idx & 31;
            int r = n0 + e; if (r >= N_NODES_C) r = N_NODES_C - 1;
            float4 v = *(const float4*)&xin[(size_t)r * NH + g * 4];
            __nv_bfloat16* dst = &As[e * 136 + g * 4];
            dst[0] = bf(v.x); dst[1] = bf(v.y); dst[2] = bf(v.z); dst[3] = bf(v.w);
        }
        __syncthreads();

        FragC acc[2][4];
#pragma unroll
        for (int i = 0; i < 2; i++)
#pragma unroll
            for (int j = 0; j < 4; j++) wmma::fill_fragment(acc[i][j], 0.f);

#pragma unroll
        for (int kk = 0; kk < NH; kk += 16) {
            FragA a0, a1;
            wmma::load_matrix_sync(a0, &As[(wy * 32) * 136 + kk], 136);
            wmma::load_matrix_sync(a1, &As[(wy * 32 + 16) * 136 + kk], 136);
#pragma unroll
            for (int j = 0; j < 4; j++) {
                FragB bfr;
                wmma::load_matrix_sync(bfr, &Bs[kk * 264 + wx * 64 + j * 16], 264);
                wmma::mma_sync(acc[0][j], a0, bfr, acc[0][j]);
                wmma::mma_sync(acc[1][j], a1, bfr, acc[1][j]);
            }
        }
#pragma unroll
        for (int i = 0; i < 2; i++) {
            int row0 = n0 + wy * 32 + i * 16;
            if (row0 + 16 <= N_NODES_C) {
#pragma unroll
                for (int j = 0; j < 4; j++)
                    wmma::store_matrix_sync(&g_Y[(size_t)row0 * 256 + wx * 64 + j * 16],
                                            acc[i][j], 256, wmma::mem_row_major);
            }
        }
    }
}

// ================= stats pass: warp-per-node over CSR (r-side loads amortized) ========
__global__ void __launch_bounds__(256)
k_stats(const float* __restrict__ xin, const float* __restrict__ W1c) {
    __shared__ float w1c[6 * 128];
    __shared__ float red[2 * 128];

    int tid = threadIdx.x;
    int warp = tid >> 5, lane = tid & 31;
    for (int i = tid; i < 6 * 128; i += 256) w1c[i] = W1c[i];
    if (tid < 256) red[tid] = 0.f;
    __syncthreads();

    float acc_s[4] = {0.f, 0.f, 0.f, 0.f};
    float acc_q[4] = {0.f, 0.f, 0.f, 0.f};
    int col = lane * 4;
    float sgn0 = (lane == 0) ? 1.f : -1.f;

    int gw = blockIdx.x * 8 + warp;
    int tw = gridDim.x * 8;
    for (int n = gw; n < N_NODES_C; n += tw) {
        float4 xr = *(const float4*)&xin[(size_t)n * NH + col];   // resident per node
        float4 y1 = *(const float4*)&g_Y[(size_t)n * 256 + col];
        int beg = g_rowptr[n], end = g_rowptr[n + 1];
        for (int j = beg; j < end; j++) {
            int c = g_colj[j];
            float4 xc = *(const float4*)&xin[(size_t)c * NH + col];
            float4 y2 = *(const float4*)&g_Y[(size_t)c * 256 + 128 + col];
            float dx = xr.x - xc.x, dy = xr.y - xc.y, dz = xr.z - xc.z, dw = xr.w - xc.w;
            float dd = sgn0 * dx * dx - dy * dy - dz * dz - dw * dw;
            float ij = sgn0 * xr.x * xc.x - xr.y * xc.y - xr.z * xc.z - xr.w * xc.w;
#pragma unroll
            for (int o = 16; o; o >>= 1) {
                dd += __shfl_xor_sync(0xffffffffu, dd, o);
                ij += __shfl_xor_sync(0xffffffffu, ij, o);
            }
            float nrm = psi_f(dd), dt = psi_f(ij);

            float4 eav = *(const float4*)&g_eap[(size_t)j * 4];
            float hv[4] = {y1.x + y2.x, y1.y + y2.y, y1.z + y2.z, y1.w + y2.w};
            float ho[4];
#pragma unroll
            for (int q = 0; q < 4; q++) {
                int cc = col + q;
                float h = hv[q];
                h = fmaf(eav.x, w1c[cc], h);
                h = fmaf(eav.y, w1c[128 + cc], h);
                h = fmaf(eav.z, w1c[256 + cc], h);
                h = fmaf(eav.w, w1c[384 + cc], h);
                h = fmaf(nrm, w1c[512 + cc], h);
                h = fmaf(dt, w1c[640 + cc], h);
                ho[q] = h;
                acc_s[q] += h;
                acc_q[q] = fmaf(h, h, acc_q[q]);
            }
            __nv_bfloat162 h01 = __floats2bfloat162_rn(ho[0], ho[1]);
            __nv_bfloat162 h23 = __floats2bfloat162_rn(ho[2], ho[3]);
            uint2 pk;
            pk.x = *(unsigned int*)&h01;
            pk.y = *(unsigned int*)&h23;
            *(uint2*)&g_h[(size_t)j * NH + col] = pk;
        }
    }
#pragma unroll
    for (int q = 0; q < 4; q++) {
        atomicAdd(&red[col + q], acc_s[q]);
        atomicAdd(&red[128 + col + q], acc_q[q]);
    }
    __syncthreads();
    if (tid < 256) atomicAdd(&g_stats[tid], red[tid]);
}

// ================= BN finalize =========================================================
__global__ void k_bnfin(const float* __restrict__ gamma, const float* __restrict__ beta) {
    int c = threadIdx.x;
    float inv = 1.f / (float)N_EDGES_C;
    float mean = g_stats[c] * inv;
    float var = g_stats[NH + c] * inv - mean * mean;
    float sc = gamma[c] * rsqrtf(var + BN_EPS);
    g_bnA[c] = sc;
    g_bnB[c] = beta[c] - mean * sc;
    g_stats[c] = 0.f;
    g_stats[NH + c] = 0.f;
}

// ================= fused edge MLP: FOUR 4-warp pipelines per CTA (slot order) =========
#define BARG() asm volatile("bar.sync %0, 128;" :: "r"(group + 1) : "memory")

__global__ void __launch_bounds__(512, 1)
k_fused(const float* __restrict__ W2, const float* __restrict__ b2,
        const float* __restrict__ Wa, const float* __restrict__ ba,
        const float* __restrict__ Wb,
        const float* __restrict__ Wm, const float* __restrict__ bm) {
    extern __shared__ __align__(16) char smraw[];
    __nv_bfloat16* W2s = (__nv_bfloat16*)smraw;       // 128 x 136
    __nv_bfloat16* Was = W2s + 128 * 136;             // 128 x 136
    __nv_bfloat16* Sall = Was + 128 * 136;            // 4 x (32 x 136) bf16
    float* Sfall = (float*)(Sall + 4 * 32 * 136);     // 4 x (32 x 132) fp32
    float* p_bnA = Sfall + 4 * 32 * 132;
    float* p_bnB = p_bnA + NH;
    float* p_b2  = p_bnB + NH;
    float* p_ba  = p_b2 + NH;
    float* p_Wm  = p_ba + NH;
    float* p_Wb  = p_Wm + NH;
    float* wg_all = p_Wb + NH;                        // 4 x 32

    int tid = threadIdx.x;
    int warp = tid >> 5, lane = tid & 31;
    int group = warp >> 2;                 // 0..3
    int gwarp = warp & 3;                  // 0..3 (column quarter)
    float bmv = bm[0];

    __nv_bfloat16* S  = Sall + group * 32 * 136;
    float*         Sf = Sfall + group * 32 * 132;
    float*         wgv = wg_all + group * 32;

    for (int idx = tid; idx < NH * NH; idx += 512) {
        int k = idx >> 7, c = idx & 127;
        W2s[k * 136 + c] = bf(W2[idx]);
        Was[k * 136 + c] = bf(Wa[idx]);
    }
    if (tid < NH) {
        p_bnA[tid] = g_bnA[tid];
        p_bnB[tid] = g_bnB[tid];
        p_b2[tid]  = b2[tid];
        p_ba[tid]  = ba[tid];
        p_Wm[tid]  = Wm[tid];
        p_Wb[tid]  = Wb[tid];
    }
    __syncthreads();

    const int NT = N_EDGES_C / 32;          // 10000
    int tid_g = tid & 127;

    for (int tile = blockIdx.x * 4 + group; tile < NT; tile += GRID_P * 4) {
        int e0 = tile * 32;

        // phase 1: sequential bf16 hpre stream; BN + ReLU -> S
        for (int idx = tid_g; idx < 32 * 16; idx += 128) {
            int e = idx >> 4, g = idx & 15;
            uint4 u = *(const uint4*)&g_h[(size_t)(e0 + e) * NH + g * 8];
            __nv_bfloat162* hp = (__nv_bfloat162*)&u;
            int cc0 = g * 8;
            uint4 outp;
            __nv_bfloat162* op = (__nv_bfloat162*)&outp;
#pragma unroll
            for (int q = 0; q < 4; q++) {
                float2 f = __bfloat1622float2(hp[q]);
                int c0 = cc0 + q * 2;
                float v0 = fmaxf(fmaf(f.x, p_bnA[c0 + 0], p_bnB[c0 + 0]), 0.f);
                float v1 = fmaxf(fmaf(f.y, p_bnA[c0 + 1], p_bnB[c0 + 1]), 0.f);
                op[q] = __floats2bfloat162_rn(v0, v1);
            }
            *(uint4*)&S[e * 136 + g * 8] = outp;
        }
        BARG();

        // phase 2: Sf = S @ W2
        {
            FragC acc[2][2];
#pragma unroll
            for (int i = 0; i < 2; i++)
#pragma unroll
                for (int j = 0; j < 2; j++) wmma::fill_fragment(acc[i][j], 0.f);
#pragma unroll
            for (int kk = 0; kk < NH; kk += 16) {
                FragA a0, a1; FragB b0, b1;
                wmma::load_matrix_sync(a0, &S[0 * 136 + kk], 136);
                wmma::load_matrix_sync(a1, &S[16 * 136 + kk], 136);
                wmma::load_matrix_sync(b0, &W2s[kk * 136 + gwarp * 32], 136);
                wmma::load_matrix_sync(b1, &W2s[kk * 136 + gwarp * 32 + 16], 136);
                wmma::mma_sync(acc[0][0], a0, b0, acc[0][0]);
                wmma::mma_sync(acc[0][1], a0, b1, acc[0][1]);
                wmma::mma_sync(acc[1][0], a1, b0, acc[1][0]);
                wmma::mma_sync(acc[1][1], a1, b1, acc[1][1]);
            }
#pragma unroll
            for (int i = 0; i < 2; i++)
#pragma unroll
                for (int j = 0; j < 2; j++)
                    wmma::store_matrix_sync(&Sf[(i * 16) * 132 + gwarp * 32 + j * 16],
                                            acc[i][j], 132, wmma::mem_row_major);
        }
        BARG();

        // phase 3: bias + ReLU -> S; gate -> wgv
#pragma unroll
        for (int t = 0; t < 8; t++) {
            int e = gwarp * 8 + t;
            float v[4];
            float p = 0.f;
#pragma unroll
            for (int u = 0; u < 4; u++) {
                int c = lane + 32 * u;
                v[u] = fmaxf(Sf[e * 132 + c] + p_b2[c], 0.f);
                p = fmaf(v[u], p_Wm[c], p);
            }
#pragma unroll
            for (int o = 16; o; o >>= 1) p += __shfl_xor_sync(0xffffffffu, p, o);
            if (lane == 0) wgv[e] = sigmoid_f(p + bmv);
#pragma unroll
            for (int u = 0; u < 4; u++) {
                int c = lane + 32 * u;
                S[e * 136 + c] = bf(v[u]);
            }
        }
        BARG();

        // phase 4: Sf = S @ Wa
        {
            FragC acc[2][2];
#pragma unroll
            for (int i = 0; i < 2; i++)
#pragma unroll
                for (int j = 0; j < 2; j++) wmma::fill_fragment(acc[i][j], 0.f);
#pragma unroll
            for (int kk = 0; kk < NH; kk += 16) {
                FragA a0, a1; FragB b0, b1;
                wmma::load_matrix_sync(a0, &S[0 * 136 + kk], 136);
                wmma::load_matrix_sync(a1, &S[16 * 136 + kk], 136);
                wmma::load_matrix_sync(b0, &Was[kk * 136 + gwarp * 32], 136);
                wmma::load_matrix_sync(b1, &Was[kk * 136 + gwarp * 32 + 16], 136);
                wmma::mma_sync(acc[0][0], a0, b0, acc[0][0]);
                wmma::mma_sync(acc[0][1], a0, b1, acc[0][1]);
                wmma::mma_sync(acc[1][0], a1, b0, acc[1][0]);
                wmma::mma_sync(acc[1][1], a1, b1, acc[1][1]);
            }
#pragma unroll
            for (int i = 0; i < 2; i++)
#pragma unroll
                for (int j = 0; j < 2; j++)
                    wmma::store_matrix_sync(&Sf[(i * 16) * 132 + gwarp * 32 + j * 16],
                                            acc[i][j], 132, wmma::mem_row_major);
        }
        BARG();

        // phase 5: s = ReLU(wg * Sf + ba) . Wb -> g_s (slot order)
#pragma unroll
        for (int t = 0; t < 8; t++) {
            int e = gwarp * 8 + t;
            float wg = wgv[e];
            float p = 0.f;
#pragma unroll
            for (int u = 0; u < 4; u++) {
                int c = lane + 32 * u;
                p = fmaf(fmaxf(fmaf(wg, Sf[e * 132 + c], p_ba[c]), 0.f), p_Wb[c], p);
            }
#pragma unroll
            for (int o = 16; o; o >>= 1) p += __shfl_xor_sync(0xffffffffu, p, o);
            if (lane == 0) g_s[e0 + e] = p;
        }
        BARG();
    }
}

// ================= aggregation (slot order; + fused head on final layer) ==============
__global__ void __launch_bounds__(256)
k_agg(const float* __restrict__ xin, float* __restrict__ xout,
      int is_final,
      const float* __restrict__ We, const float* __restrict__ be,
      float* __restrict__ out) {
    int n = blockIdx.x * 8 + (threadIdx.x >> 5);
    if (n >= N_NODES_C) return;
    int lane = threadIdx.x & 31;
    float4 xi = *(const float4*)&xin[(size_t)n * NH + lane * 4];
    float4 acc = xi;
    int beg = g_rowptr[n], end = g_rowptr[n + 1];
    for (int j = beg; j < end; j++) {
        float s = g_s[j];
        int c = g_colj[j];
        float4 xc = *(const float4*)&xin[(size_t)c * NH + lane * 4];
        acc.x += fminf(fmaxf((xi.x - xc.x) * s, -100.f), 100.f);
        acc.y += fminf(fmaxf((xi.y - xc.y) * s, -100.f), 100.f);
        acc.z += fminf(fmaxf((xi.z - xc.z) * s, -100.f), 100.f);
        acc.w += fminf(fmaxf((xi.w - xc.w) * s, -100.f), 100.f);
    }
    if (is_final) {
        int k0 = lane * 4;
        float p0 = acc.x * We[k0 * 2] + acc.y * We[(k0 + 1) * 2]
                 + acc.z * We[(k0 + 2) * 2] + acc.w * We[(k0 + 3) * 2];
        float p1 = acc.x * We[k0 * 2 + 1] + acc.y * We[(k0 + 1) * 2 + 1]
                 + acc.z * We[(k0 + 2) * 2 + 1] + acc.w * We[(k0 + 3) * 2 + 1];
#pragma unroll
        for (int o = 16; o; o >>= 1) {
            p0 += __shfl_xor_sync(0xffffffffu, p0, o);
            p1 += __shfl_xor_sync(0xffffffffu, p1, o);
        }
        if (lane == 0) {
            out[(size_t)n * 2 + 0] = sigmoid_f(p0 + be[0]);
            out[(size_t)n * 2 + 1] = sigmoid_f(p1 + be[1]);
        }
    } else {
        *(float4*)&xout[(size_t)n * NH + lane * 4] = acc;
    }
}

// ================= launch ==============================================================
extern "C" void kernel_launch(void* const* d_in, const int* in_sizes, int n_in,
                              void* d_out, int out_size) {
    (void)in_sizes; (void)n_in; (void)out_size;
    const float* x     = (const float*)d_in[0];
    const int*   ei    = (const int*)d_in[1];
    const float* ea    = (const float*)d_in[2];
    const float* W1    = (const float*)d_in[3];
    const float* gamma = (const float*)d_in[4];
    const float* beta  = (const float*)d_in[5];
    const float* W2    = (const float*)d_in[6];
    const float* b2    = (const float*)d_in[7];
    const float* Wa    = (const float*)d_in[8];
    const float* ba    = (const float*)d_in[9];
    const float* Wb    = (const float*)d_in[10];
    const float* Wm    = (const float*)d_in[11];
    const float* bm    = (const float*)d_in[12];
    const float* We    = (const float*)d_in[13];
    const float* be    = (const float*)d_in[14];
    float* out = (float*)d_out;

    const int smem_node  = 128 * 264 * 2 + 64 * 136 * 2;
    const int smem_fused = 2 * 128 * 136 * 2
                         + 4 * 32 * 136 * 2
                         + 4 * 32 * 132 * 4
                         + (6 * 128 + 128) * 4;
    cudaFuncSetAttribute(k_node,  cudaFuncAttributeMaxDynamicSharedMemorySize, smem_node);
    cudaFuncSetAttribute(k_fused, cudaFuncAttributeMaxDynamicSharedMemorySize, smem_fused);

    void *px = nullptr, *pcnt = nullptr, *pstats = nullptr, *px2 = nullptr;
    cudaGetSymbolAddress(&px, g_x);
    cudaGetSymbolAddress(&px2, g_x2);
    cudaGetSymbolAddress(&pcnt, g_cnt);
    cudaGetSymbolAddress(&pstats, g_stats);

    cudaMemcpyAsync(px, x, sizeof(float) * N_NODES_C * NH, cudaMemcpyDeviceToDevice, 0);
    cudaMemsetAsync(pcnt, 0, N_NODES_C * sizeof(int), 0);
    cudaMemsetAsync(pstats, 0, 2 * NH * sizeof(float), 0);

    k_hist<<<(N_EDGES_C + 255) / 256, 256>>>(ei);
    k_scan<<<1, 1024>>>();
    k_fillcsr<<<(N_EDGES_C + 255) / 256, 256>>>(ei);
    k_sortseg<<<(N_NODES_C + 255) / 256, 256>>>();
    k_perm<<<(N_EDGES_C + 255) / 256, 256>>>(ei, ea);

    float* bufA = (float*)px;
    float* bufB = (float*)px2;

    for (int l = 0; l < NLAYERS; l++) {
        const float* W1l = W1 + (size_t)l * DIN * NH;
        const float* xin  = (l & 1) ? bufB : bufA;
        float*       xout = (l & 1) ? bufA : bufB;
        int is_final = (l == NLAYERS - 1);
        k_node<<<GRID_P * 2, 256, smem_node>>>(xin, W1l);
        k_stats<<<1184, 256>>>(xin, W1l + 256 * NH);
        k_bnfin<<<1, 128>>>(gamma + l * NH, beta + l * NH);
        k_fused<<<GRID_P, 512, smem_fused>>>(W2 + (size_t)l * NH * NH, b2 + l * NH,
                                             Wa + (size_t)l * NH * NH, ba + l * NH,
                                             Wb + l * NH,
                                             Wm + l * NH, bm + l);
        k_agg<<<(N_NODES_C + 7) / 8, 256>>>(xin, xout, is_final, We, be, out);
    }
}

// round 12
// speedup vs baseline: 1.0801x; 1.0641x over previous
#include <cuda_runtime.h>
#include <cuda_bf16.h>
#include <mma.h>
#include <math.h>

using namespace nvcuda;

#define N_NODES_C 20000
#define N_EDGES_C 320000
#define NH 128
#define DIN 262
#define NLAYERS 3
#define BN_EPS 1e-5f
#define GRID_P 148

// ---------------- scratch ----------------
__device__ float g_x[N_NODES_C * NH];
__device__ float g_x2[N_NODES_C * NH];
__device__ float g_Y[(size_t)N_NODES_C * 256];              // [Y1 | Y2] per node
__device__ __nv_bfloat16 g_h[(size_t)N_EDGES_C * NH];       // hpre (bf16, slot order)
__device__ float g_s[N_EDGES_C];                            // per-slot phi_x scalar
__device__ float g_eap[N_EDGES_C * 4];                      // permuted edge_attr
__device__ int   g_colj[N_EDGES_C];                         // permuted col index
__device__ float g_stats[2 * NH];
__device__ int   g_cnt[N_NODES_C];
__device__ int   g_rowptr[N_NODES_C + 1];
__device__ int   g_eidx[N_EDGES_C];

__device__ __forceinline__ float psi_f(float z) {
    return copysignf(log1pf(fabsf(z)), z);
}
__device__ __forceinline__ float sigmoid_f(float z) {
    return 1.0f / (1.0f + expf(-z));
}
__device__ __forceinline__ __nv_bfloat16 bf(float x) { return __float2bfloat16(x); }

typedef wmma::fragment<wmma::matrix_a, 16, 16, 16, __nv_bfloat16, wmma::row_major> FragA;
typedef wmma::fragment<wmma::matrix_b, 16, 16, 16, __nv_bfloat16, wmma::row_major> FragB;
typedef wmma::fragment<wmma::accumulator, 16, 16, 16, float> FragC;

// ================= CSR build (once per launch) ========================================
__global__ void k_hist(const int* __restrict__ ei) {
    int e = blockIdx.x * 256 + threadIdx.x;
    if (e < N_EDGES_C) atomicAdd(&g_cnt[ei[e]], 1);
}

__global__ void k_scan() {
    __shared__ int part[1024];
    int t = threadIdx.x;
    int base = t * 20;
    int s = 0;
    for (int i = 0; i < 20; i++) {
        int idx = base + i;
        if (idx < N_NODES_C) s += g_cnt[idx];
    }
    part[t] = s;
    __syncthreads();
    for (int off = 1; off < 1024; off <<= 1) {
        int v = (t >= off) ? part[t - off] : 0;
        __syncthreads();
        part[t] += v;
        __syncthreads();
    }
    int run = (t == 0) ? 0 : part[t - 1];
    for (int i = 0; i < 20; i++) {
        int idx = base + i;
        if (idx <= N_NODES_C) g_rowptr[idx] = run;
        if (idx < N_NODES_C) run += g_cnt[idx];
    }
    for (int i = 0; i < 20; i++) {
        int idx = base + i;
        if (idx < N_NODES_C) g_cnt[idx] = 0;
    }
}

__global__ void k_fillcsr(const int* __restrict__ ei) {
    int e = blockIdx.x * 256 + threadIdx.x;
    if (e < N_EDGES_C) {
        int r = ei[e];
        int slot = g_rowptr[r] + atomicAdd(&g_cnt[r], 1);
        g_eidx[slot] = e;
    }
}

__global__ void k_sortseg() {
    int n = blockIdx.x * 256 + threadIdx.x;
    if (n >= N_NODES_C) return;
    int beg = g_rowptr[n], end = g_rowptr[n + 1];
    for (int i = beg + 1; i < end; i++) {
        int v = g_eidx[i], j = i - 1;
        while (j >= beg && g_eidx[j] > v) { g_eidx[j + 1] = g_eidx[j]; j--; }
        g_eidx[j + 1] = v;
    }
}

__global__ void k_perm(const int* __restrict__ ei, const float* __restrict__ ea) {
    int j = blockIdx.x * 256 + threadIdx.x;
    if (j < N_EDGES_C) {
        int e = g_eidx[j];
        g_colj[j] = ei[N_EDGES_C + e];
        *(float4*)&g_eap[(size_t)j * 4] = *(const float4*)&ea[(size_t)e * 4];
    }
}

// ================= node GEMM: Y = X @ [W1a | W1b] (2 CTAs/SM) =========================
__global__ void __launch_bounds__(256, 2)
k_node(const float* __restrict__ xin, const float* __restrict__ W1) {
    extern __shared__ __align__(16) char smraw[];
    __nv_bfloat16* Bs = (__nv_bfloat16*)smraw;        // 128 x 264
    __nv_bfloat16* As = Bs + 128 * 264;               // 64 x 136

    int tid = threadIdx.x;
    int warp = tid >> 5;
    int wy = warp >> 2, wx = warp & 3;

    for (int idx = tid; idx < 128 * 256; idx += 256) {
        int k = idx >> 8, c = idx & 255;
        float v = (c < 128) ? W1[(size_t)k * NH + c] : W1[(size_t)(128 + k) * NH + (c - 128)];
        Bs[k * 264 + c] = bf(v);
    }

    const int NT = (N_NODES_C + 63) / 64;   // 313
    for (int tile = blockIdx.x; tile < NT; tile += GRID_P * 2) {
        int n0 = tile * 64;
        __syncthreads();
        for (int idx = tid; idx < 64 * 32; idx += 256) {
            int e = idx >> 5, g = idx & 31;
            int r = n0 + e; if (r >= N_NODES_C) r = N_NODES_C - 1;
            float4 v = *(const float4*)&xin[(size_t)r * NH + g * 4];
            __nv_bfloat16* dst = &As[e * 136 + g * 4];
            dst[0] = bf(v.x); dst[1] = bf(v.y); dst[2] = bf(v.z); dst[3] = bf(v.w);
        }
        __syncthreads();

        FragC acc[2][4];
#pragma unroll
        for (int i = 0; i < 2; i++)
#pragma unroll
            for (int j = 0; j < 4; j++) wmma::fill_fragment(acc[i][j], 0.f);

#pragma unroll
        for (int kk = 0; kk < NH; kk += 16) {
            FragA a0, a1;
            wmma::load_matrix_sync(a0, &As[(wy * 32) * 136 + kk], 136);
            wmma::load_matrix_sync(a1, &As[(wy * 32 + 16) * 136 + kk], 136);
#pragma unroll
            for (int j = 0; j < 4; j++) {
                FragB bfr;
                wmma::load_matrix_sync(bfr, &Bs[kk * 264 + wx * 64 + j * 16], 264);
                wmma::mma_sync(acc[0][j], a0, bfr, acc[0][j]);
                wmma::mma_sync(acc[1][j], a1, bfr, acc[1][j]);
            }
        }
#pragma unroll
        for (int i = 0; i < 2; i++) {
            int row0 = n0 + wy * 32 + i * 16;
            if (row0 + 16 <= N_NODES_C) {
#pragma unroll
                for (int j = 0; j < 4; j++)
                    wmma::store_matrix_sync(&g_Y[(size_t)row0 * 256 + wx * 64 + j * 16],
                                            acc[i][j], 256, wmma::mem_row_major);
            }
        }
    }
}

// ================= stats pass: warp-per-node over CSR =================================
__global__ void __launch_bounds__(256)
k_stats(const float* __restrict__ xin, const float* __restrict__ W1c) {
    __shared__ float w1c[6 * 128];
    __shared__ float red[2 * 128];

    int tid = threadIdx.x;
    int warp = tid >> 5, lane = tid & 31;
    for (int i = tid; i < 6 * 128; i += 256) w1c[i] = W1c[i];
    if (tid < 256) red[tid] = 0.f;
    __syncthreads();

    float acc_s[4] = {0.f, 0.f, 0.f, 0.f};
    float acc_q[4] = {0.f, 0.f, 0.f, 0.f};
    int col = lane * 4;
    float sgn0 = (lane == 0) ? 1.f : -1.f;

    int gw = blockIdx.x * 8 + warp;
    int tw = gridDim.x * 8;
    for (int n = gw; n < N_NODES_C; n += tw) {
        float4 xr = *(const float4*)&xin[(size_t)n * NH + col];
        float4 y1 = *(const float4*)&g_Y[(size_t)n * 256 + col];
        int beg = g_rowptr[n], end = g_rowptr[n + 1];
        for (int j = beg; j < end; j++) {
            int c = g_colj[j];
            float4 xc = *(const float4*)&xin[(size_t)c * NH + col];
            float4 y2 = *(const float4*)&g_Y[(size_t)c * 256 + 128 + col];
            float dx = xr.x - xc.x, dy = xr.y - xc.y, dz = xr.z - xc.z, dw = xr.w - xc.w;
            float dd = sgn0 * dx * dx - dy * dy - dz * dz - dw * dw;
            float ij = sgn0 * xr.x * xc.x - xr.y * xc.y - xr.z * xc.z - xr.w * xc.w;
#pragma unroll
            for (int o = 16; o; o >>= 1) {
                dd += __shfl_xor_sync(0xffffffffu, dd, o);
                ij += __shfl_xor_sync(0xffffffffu, ij, o);
            }
            float nrm = psi_f(dd), dt = psi_f(ij);

            float4 eav = *(const float4*)&g_eap[(size_t)j * 4];
            float hv[4] = {y1.x + y2.x, y1.y + y2.y, y1.z + y2.z, y1.w + y2.w};
            float ho[4];
#pragma unroll
            for (int q = 0; q < 4; q++) {
                int cc = col + q;
                float h = hv[q];
                h = fmaf(eav.x, w1c[cc], h);
                h = fmaf(eav.y, w1c[128 + cc], h);
                h = fmaf(eav.z, w1c[256 + cc], h);
                h = fmaf(eav.w, w1c[384 + cc], h);
                h = fmaf(nrm, w1c[512 + cc], h);
                h = fmaf(dt, w1c[640 + cc], h);
                ho[q] = h;
                acc_s[q] += h;
                acc_q[q] = fmaf(h, h, acc_q[q]);
            }
            __nv_bfloat162 h01 = __floats2bfloat162_rn(ho[0], ho[1]);
            __nv_bfloat162 h23 = __floats2bfloat162_rn(ho[2], ho[3]);
            uint2 pk;
            pk.x = *(unsigned int*)&h01;
            pk.y = *(unsigned int*)&h23;
            *(uint2*)&g_h[(size_t)j * NH + col] = pk;
        }
    }
#pragma unroll
    for (int q = 0; q < 4; q++) {
        atomicAdd(&red[col + q], acc_s[q]);
        atomicAdd(&red[128 + col + q], acc_q[q]);
    }
    __syncthreads();
    if (tid < 256) atomicAdd(&g_stats[tid], red[tid]);
}

// ================= fused edge MLP: FOUR 4-warp pipelines, in-CTA BN finalize ==========
#define BARG() asm volatile("bar.sync %0, 128;" :: "r"(group + 1) : "memory")

__global__ void __launch_bounds__(512, 1)
k_fused(const float* __restrict__ gamma, const float* __restrict__ beta,
        const float* __restrict__ W2, const float* __restrict__ b2,
        const float* __restrict__ Wa, const float* __restrict__ ba,
        const float* __restrict__ Wb,
        const float* __restrict__ Wm, const float* __restrict__ bm) {
    extern __shared__ __align__(16) char smraw[];
    __nv_bfloat16* W2s = (__nv_bfloat16*)smraw;       // 128 x 136
    __nv_bfloat16* Was = W2s + 128 * 136;             // 128 x 136
    __nv_bfloat16* Sall = Was + 128 * 136;            // 4 x (32 x 136) bf16
    float* Sfall = (float*)(Sall + 4 * 32 * 136);     // 4 x (32 x 132) fp32
    float* p_bnA = Sfall + 4 * 32 * 132;
    float* p_bnB = p_bnA + NH;
    float* p_b2  = p_bnB + NH;
    float* p_ba  = p_b2 + NH;
    float* p_Wm  = p_ba + NH;
    float* p_Wb  = p_Wm + NH;
    float* wg_all = p_Wb + NH;                        // 4 x 32

    int tid = threadIdx.x;
    int warp = tid >> 5, lane = tid & 31;
    int group = warp >> 2;                 // 0..3
    int gwarp = warp & 3;                  // 0..3 (column quarter)
    float bmv = bm[0];

    __nv_bfloat16* S  = Sall + group * 32 * 136;
    float*         Sf = Sfall + group * 32 * 132;
    float*         wgv = wg_all + group * 32;

    for (int idx = tid; idx < NH * NH; idx += 512) {
        int k = idx >> 7, c = idx & 127;
        W2s[k * 136 + c] = bf(W2[idx]);
        Was[k * 136 + c] = bf(Wa[idx]);
    }
    if (tid < NH) {
        // BN finalize in-CTA (replaces k_bnfin kernel)
        float inv = 1.f / (float)N_EDGES_C;
        float mean = g_stats[tid] * inv;
        float var = g_stats[NH + tid] * inv - mean * mean;
        float sc = gamma[tid] * rsqrtf(var + BN_EPS);
        p_bnA[tid] = sc;
        p_bnB[tid] = beta[tid] - mean * sc;
        p_b2[tid]  = b2[tid];
        p_ba[tid]  = ba[tid];
        p_Wm[tid]  = Wm[tid];
        p_Wb[tid]  = Wb[tid];
    }
    __syncthreads();

    const int NT = N_EDGES_C / 32;          // 10000
    int tid_g = tid & 127;
    int pe = tid_g >> 4, pg = tid_g & 15;   // fixed (edge, group8) for prefetch slots

    int tile = blockIdx.x * 4 + group;
    uint4 pre[4];
    if (tile < NT) {
#pragma unroll
        for (int it = 0; it < 4; it++) {
            int e = pe + it * 8;
            pre[it] = *(const uint4*)&g_h[(size_t)(tile * 32 + e) * NH + pg * 8];
        }
    }

    for (; tile < NT; tile += GRID_P * 4) {
        int e0 = tile * 32;

        // phase 1: convert prefetched hpre; BN + ReLU -> S
#pragma unroll
        for (int it = 0; it < 4; it++) {
            int e = pe + it * 8;
            __nv_bfloat162* hp = (__nv_bfloat162*)&pre[it];
            int cc0 = pg * 8;
            uint4 outp;
            __nv_bfloat162* op = (__nv_bfloat162*)&outp;
#pragma unroll
            for (int q = 0; q < 4; q++) {
                float2 f = __bfloat1622float2(hp[q]);
                int c0 = cc0 + q * 2;
                float v0 = fmaxf(fmaf(f.x, p_bnA[c0 + 0], p_bnB[c0 + 0]), 0.f);
                float v1 = fmaxf(fmaf(f.y, p_bnA[c0 + 1], p_bnB[c0 + 1]), 0.f);
                op[q] = __floats2bfloat162_rn(v0, v1);
            }
            *(uint4*)&S[e * 136 + pg * 8] = outp;
        }
        // prefetch next tile's hpre (hidden behind phases 2-5)
        {
            int ntile = tile + GRID_P * 4;
            if (ntile < NT) {
#pragma unroll
                for (int it = 0; it < 4; it++) {
                    int e = pe + it * 8;
                    pre[it] = *(const uint4*)&g_h[(size_t)(ntile * 32 + e) * NH + pg * 8];
                }
            }
        }
        BARG();

        // phase 2: Sf = S @ W2
        {
            FragC acc[2][2];
#pragma unroll
            for (int i = 0; i < 2; i++)
#pragma unroll
                for (int j = 0; j < 2; j++) wmma::fill_fragment(acc[i][j], 0.f);
#pragma unroll
            for (int kk = 0; kk < NH; kk += 16) {
                FragA a0, a1; FragB b0, b1;
                wmma::load_matrix_sync(a0, &S[0 * 136 + kk], 136);
                wmma::load_matrix_sync(a1, &S[16 * 136 + kk], 136);
                wmma::load_matrix_sync(b0, &W2s[kk * 136 + gwarp * 32], 136);
                wmma::load_matrix_sync(b1, &W2s[kk * 136 + gwarp * 32 + 16], 136);
                wmma::mma_sync(acc[0][0], a0, b0, acc[0][0]);
                wmma::mma_sync(acc[0][1], a0, b1, acc[0][1]);
                wmma::mma_sync(acc[1][0], a1, b0, acc[1][0]);
                wmma::mma_sync(acc[1][1], a1, b1, acc[1][1]);
            }
#pragma unroll
            for (int i = 0; i < 2; i++)
#pragma unroll
                for (int j = 0; j < 2; j++)
                    wmma::store_matrix_sync(&Sf[(i * 16) * 132 + gwarp * 32 + j * 16],
                                            acc[i][j], 132, wmma::mem_row_major);
        }
        BARG();

        // phase 3: bias + ReLU -> S; gate -> wgv
#pragma unroll
        for (int t = 0; t < 8; t++) {
            int e = gwarp * 8 + t;
            float v[4];
            float p = 0.f;
#pragma unroll
            for (int u = 0; u < 4; u++) {
                int c = lane + 32 * u;
                v[u] = fmaxf(Sf[e * 132 + c] + p_b2[c], 0.f);
                p = fmaf(v[u], p_Wm[c], p);
            }
#pragma unroll
            for (int o = 16; o; o >>= 1) p += __shfl_xor_sync(0xffffffffu, p, o);
            if (lane == 0) wgv[e] = sigmoid_f(p + bmv);
#pragma unroll
            for (int u = 0; u < 4; u++) {
                int c = lane + 32 * u;
                S[e * 136 + c] = bf(v[u]);
            }
        }
        BARG();

        // phase 4: Sf = S @ Wa
        {
            FragC acc[2][2];
#pragma unroll
            for (int i = 0; i < 2; i++)
#pragma unroll
                for (int j = 0; j < 2; j++) wmma::fill_fragment(acc[i][j], 0.f);
#pragma unroll
            for (int kk = 0; kk < NH; kk += 16) {
                FragA a0, a1; FragB b0, b1;
                wmma::load_matrix_sync(a0, &S[0 * 136 + kk], 136);
                wmma::load_matrix_sync(a1, &S[16 * 136 + kk], 136);
                wmma::load_matrix_sync(b0, &Was[kk * 136 + gwarp * 32], 136);
                wmma::load_matrix_sync(b1, &Was[kk * 136 + gwarp * 32 + 16], 136);
                wmma::mma_sync(acc[0][0], a0, b0, acc[0][0]);
                wmma::mma_sync(acc[0][1], a0, b1, acc[0][1]);
                wmma::mma_sync(acc[1][0], a1, b0, acc[1][0]);
                wmma::mma_sync(acc[1][1], a1, b1, acc[1][1]);
            }
#pragma unroll
            for (int i = 0; i < 2; i++)
#pragma unroll
                for (int j = 0; j < 2; j++)
                    wmma::store_matrix_sync(&Sf[(i * 16) * 132 + gwarp * 32 + j * 16],
                                            acc[i][j], 132, wmma::mem_row_major);
        }
        BARG();

        // phase 5: s = ReLU(wg * Sf + ba) . Wb -> g_s
        // (no trailing barrier: next phase 1 touches only S/pre, disjoint from Sf/wgv;
        //  pre-phase-2 barrier orders these reads against the next Sf writes)
#pragma unroll
        for (int t = 0; t < 8; t++) {
            int e = gwarp * 8 + t;
            float wg = wgv[e];
            float p = 0.f;
#pragma unroll
            for (int u = 0; u < 4; u++) {
                int c = lane + 32 * u;
                p = fmaf(fmaxf(fmaf(wg, Sf[e * 132 + c], p_ba[c]), 0.f), p_Wb[c], p);
            }
#pragma unroll
            for (int o = 16; o; o >>= 1) p += __shfl_xor_sync(0xffffffffu, p, o);
            if (lane == 0) g_s[e0 + e] = p;
        }
    }
}

// ================= aggregation (slot order; fused head; resets stats) ================
__global__ void __launch_bounds__(256)
k_agg(const float* __restrict__ xin, float* __restrict__ xout,
      int is_final,
      const float* __restrict__ We, const float* __restrict__ be,
      float* __restrict__ out) {
    if (blockIdx.x == 0 && threadIdx.x < 2 * NH) g_stats[threadIdx.x] = 0.f;
    int n = blockIdx.x * 8 + (threadIdx.x >> 5);
    if (n >= N_NODES_C) return;
    int lane = threadIdx.x & 31;
    float4 xi = *(const float4*)&xin[(size_t)n * NH + lane * 4];
    float4 acc = xi;
    int beg = g_rowptr[n], end = g_rowptr[n + 1];
    for (int j = beg; j < end; j++) {
        float s = g_s[j];
        int c = g_colj[j];
        float4 xc = *(const float4*)&xin[(size_t)c * NH + lane * 4];
        acc.x += fminf(fmaxf((xi.x - xc.x) * s, -100.f), 100.f);
        acc.y += fminf(fmaxf((xi.y - xc.y) * s, -100.f), 100.f);
        acc.z += fminf(fmaxf((xi.z - xc.z) * s, -100.f), 100.f);
        acc.w += fminf(fmaxf((xi.w - xc.w) * s, -100.f), 100.f);
    }
    if (is_final) {
        int k0 = lane * 4;
        float p0 = acc.x * We[k0 * 2] + acc.y * We[(k0 + 1) * 2]
                 + acc.z * We[(k0 + 2) * 2] + acc.w * We[(k0 + 3) * 2];
        float p1 = acc.x * We[k0 * 2 + 1] + acc.y * We[(k0 + 1) * 2 + 1]
                 + acc.z * We[(k0 + 2) * 2 + 1] + acc.w * We[(k0 + 3) * 2 + 1];
#pragma unroll
        for (int o = 16; o; o >>= 1) {
            p0 += __shfl_xor_sync(0xffffffffu, p0, o);
            p1 += __shfl_xor_sync(0xffffffffu, p1, o);
        }
        if (lane == 0) {
            out[(size_t)n * 2 + 0] = sigmoid_f(p0 + be[0]);
            out[(size_t)n * 2 + 1] = sigmoid_f(p1 + be[1]);
        }
    } else {
        *(float4*)&xout[(size_t)n * NH + lane * 4] = acc;
    }
}

// ================= launch ==============================================================
extern "C" void kernel_launch(void* const* d_in, const int* in_sizes, int n_in,
                              void* d_out, int out_size) {
    (void)in_sizes; (void)n_in; (void)out_size;
    const float* x     = (const float*)d_in[0];
    const int*   ei    = (const int*)d_in[1];
    const float* ea    = (const float*)d_in[2];
    const float* W1    = (const float*)d_in[3];
    const float* gamma = (const float*)d_in[4];
    const float* beta  = (const float*)d_in[5];
    const float* W2    = (const float*)d_in[6];
    const float* b2    = (const float*)d_in[7];
    const float* Wa    = (const float*)d_in[8];
    const float* ba    = (const float*)d_in[9];
    const float* Wb    = (const float*)d_in[10];
    const float* Wm    = (const float*)d_in[11];
    const float* bm    = (const float*)d_in[12];
    const float* We    = (const float*)d_in[13];
    const float* be    = (const float*)d_in[14];
    float* out = (float*)d_out;

    const int smem_node  = 128 * 264 * 2 + 64 * 136 * 2;
    const int smem_fused = 2 * 128 * 136 * 2
                         + 4 * 32 * 136 * 2
                         + 4 * 32 * 132 * 4
                         + (6 * 128 + 128) * 4;
    cudaFuncSetAttribute(k_node,  cudaFuncAttributeMaxDynamicSharedMemorySize, smem_node);
    cudaFuncSetAttribute(k_fused, cudaFuncAttributeMaxDynamicSharedMemorySize, smem_fused);

    void *px = nullptr, *pcnt = nullptr, *pstats = nullptr, *px2 = nullptr;
    cudaGetSymbolAddress(&px, g_x);
    cudaGetSymbolAddress(&px2, g_x2);
    cudaGetSymbolAddress(&pcnt, g_cnt);
    cudaGetSymbolAddress(&pstats, g_stats);

    cudaMemcpyAsync(px, x, sizeof(float) * N_NODES_C * NH, cudaMemcpyDeviceToDevice, 0);
    cudaMemsetAsync(pcnt, 0, N_NODES_C * sizeof(int), 0);
    cudaMemsetAsync(pstats, 0, 2 * NH * sizeof(float), 0);

    k_hist<<<(N_EDGES_C + 255) / 256, 256>>>(ei);
    k_scan<<<1, 1024>>>();
    k_fillcsr<<<(N_EDGES_C + 255) / 256, 256>>>(ei);
    k_sortseg<<<(N_NODES_C + 255) / 256, 256>>>();
    k_perm<<<(N_EDGES_C + 255) / 256, 256>>>(ei, ea);

    float* bufA = (float*)px;
    float* bufB = (float*)px2;

    for (int l = 0; l < NLAYERS; l++) {
        const float* W1l = W1 + (size_t)l * DIN * NH;
        const float* xin  = (l & 1) ? bufB : bufA;
        float*       xout = (l & 1) ? bufA : bufB;
        int is_final = (l == NLAYERS - 1);
        k_node<<<GRID_P * 2, 256, smem_node>>>(xin, W1l);
        k_stats<<<1184, 256>>>(xin, W1l + 256 * NH);
        k_fused<<<GRID_P, 512, smem_fused>>>(gamma + l * NH, beta + l * NH,
                                             W2 + (size_t)l * NH * NH, b2 + l * NH,
                                             Wa + (size_t)l * NH * NH, ba + l * NH,
                                             Wb + l * NH,
                                             Wm + l * NH, bm + l);
        k_agg<<<(N_NODES_C + 7) / 8, 256>>>(xin, xout, is_final, We, be, out);
    }
}

// round 13
// speedup vs baseline: 1.1527x; 1.0673x over previous
#include <cuda_runtime.h>
#include <cuda_bf16.h>
#include <mma.h>
#include <math.h>

using namespace nvcuda;

#define N_NODES_C 20000
#define N_EDGES_C 320000
#define NH 128
#define DIN 262
#define NLAYERS 3
#define BN_EPS 1e-5f
#define GRID_P 148

// ---------------- scratch ----------------
__device__ float g_x[N_NODES_C * NH];
__device__ float g_x2[N_NODES_C * NH];
__device__ float g_Y[(size_t)N_NODES_C * 256];              // [Y1 | Y2] per node
__device__ __nv_bfloat16 g_h[(size_t)N_EDGES_C * NH];       // hpre (bf16, slot order)
__device__ float g_s[N_EDGES_C];                            // per-slot phi_x scalar
__device__ float g_eap[N_EDGES_C * 4];                      // permuted edge_attr
__device__ int   g_colj[N_EDGES_C];                         // permuted col index
__device__ float g_stats[2 * NH];
__device__ int   g_cnt[N_NODES_C];
__device__ int   g_rowptr[N_NODES_C + 1];
__device__ int   g_eidx[N_EDGES_C];

__device__ __forceinline__ float psi_f(float z) {
    return copysignf(log1pf(fabsf(z)), z);
}
__device__ __forceinline__ float sigmoid_f(float z) {
    return 1.0f / (1.0f + expf(-z));
}
__device__ __forceinline__ __nv_bfloat16 bf(float x) { return __float2bfloat16(x); }

typedef wmma::fragment<wmma::matrix_a, 16, 16, 16, __nv_bfloat16, wmma::row_major> FragA;
typedef wmma::fragment<wmma::matrix_b, 16, 16, 16, __nv_bfloat16, wmma::row_major> FragB;
typedef wmma::fragment<wmma::accumulator, 16, 16, 16, float> FragC;

// ================= CSR build (once per launch) ========================================
__global__ void k_hist(const int* __restrict__ ei) {
    int e = blockIdx.x * 256 + threadIdx.x;
    if (e < N_EDGES_C) atomicAdd(&g_cnt[ei[e]], 1);
}

__global__ void k_scan() {
    __shared__ int part[1024];
    int t = threadIdx.x;
    int base = t * 20;
    int s = 0;
    for (int i = 0; i < 20; i++) {
        int idx = base + i;
        if (idx < N_NODES_C) s += g_cnt[idx];
    }
    part[t] = s;
    __syncthreads();
    for (int off = 1; off < 1024; off <<= 1) {
        int v = (t >= off) ? part[t - off] : 0;
        __syncthreads();
        part[t] += v;
        __syncthreads();
    }
    int run = (t == 0) ? 0 : part[t - 1];
    for (int i = 0; i < 20; i++) {
        int idx = base + i;
        if (idx <= N_NODES_C) g_rowptr[idx] = run;
        if (idx < N_NODES_C) run += g_cnt[idx];
    }
    for (int i = 0; i < 20; i++) {
        int idx = base + i;
        if (idx < N_NODES_C) g_cnt[idx] = 0;
    }
}

__global__ void k_fillcsr(const int* __restrict__ ei) {
    int e = blockIdx.x * 256 + threadIdx.x;
    if (e < N_EDGES_C) {
        int r = ei[e];
        int slot = g_rowptr[r] + atomicAdd(&g_cnt[r], 1);
        g_eidx[slot] = e;
    }
}

__global__ void k_sortseg() {
    int n = blockIdx.x * 256 + threadIdx.x;
    if (n >= N_NODES_C) return;
    int beg = g_rowptr[n], end = g_rowptr[n + 1];
    for (int i = beg + 1; i < end; i++) {
        int v = g_eidx[i], j = i - 1;
        while (j >= beg && g_eidx[j] > v) { g_eidx[j + 1] = g_eidx[j]; j--; }
        g_eidx[j + 1] = v;
    }
}

__global__ void k_perm(const int* __restrict__ ei, const float* __restrict__ ea) {
    int j = blockIdx.x * 256 + threadIdx.x;
    if (j < N_EDGES_C) {
        int e = g_eidx[j];
        g_colj[j] = ei[N_EDGES_C + e];
        *(float4*)&g_eap[(size_t)j * 4] = *(const float4*)&ea[(size_t)e * 4];
    }
}

// ================= node GEMM: Y = X @ [W1a | W1b] (2 CTAs/SM) =========================
__global__ void __launch_bounds__(256, 2)
k_node(const float* __restrict__ xin, const float* __restrict__ W1) {
    extern __shared__ __align__(16) char smraw[];
    __nv_bfloat16* Bs = (__nv_bfloat16*)smraw;        // 128 x 264
    __nv_bfloat16* As = Bs + 128 * 264;               // 64 x 136

    int tid = threadIdx.x;
    int warp = tid >> 5;
    int wy = warp >> 2, wx = warp & 3;

    for (int idx = tid; idx < 128 * 256; idx += 256) {
        int k = idx >> 8, c = idx & 255;
        float v = (c < 128) ? W1[(size_t)k * NH + c] : W1[(size_t)(128 + k) * NH + (c - 128)];
        Bs[k * 264 + c] = bf(v);
    }

    const int NT = (N_NODES_C + 63) / 64;   // 313
    for (int tile = blockIdx.x; tile < NT; tile += GRID_P * 2) {
        int n0 = tile * 64;
        __syncthreads();
        for (int idx = tid; idx < 64 * 32; idx += 256) {
            int e = idx >> 5, g = idx & 31;
            int r = n0 + e; if (r >= N_NODES_C) r = N_NODES_C - 1;
            float4 v = *(const float4*)&xin[(size_t)r * NH + g * 4];
            __nv_bfloat16* dst = &As[e * 136 + g * 4];
            dst[0] = bf(v.x); dst[1] = bf(v.y); dst[2] = bf(v.z); dst[3] = bf(v.w);
        }
        __syncthreads();

        FragC acc[2][4];
#pragma unroll
        for (int i = 0; i < 2; i++)
#pragma unroll
            for (int j = 0; j < 4; j++) wmma::fill_fragment(acc[i][j], 0.f);

#pragma unroll
        for (int kk = 0; kk < NH; kk += 16) {
            FragA a0, a1;
            wmma::load_matrix_sync(a0, &As[(wy * 32) * 136 + kk], 136);
            wmma::load_matrix_sync(a1, &As[(wy * 32 + 16) * 136 + kk], 136);
#pragma unroll
            for (int j = 0; j < 4; j++) {
                FragB bfr;
                wmma::load_matrix_sync(bfr, &Bs[kk * 264 + wx * 64 + j * 16], 264);
                wmma::mma_sync(acc[0][j], a0, bfr, acc[0][j]);
                wmma::mma_sync(acc[1][j], a1, bfr, acc[1][j]);
            }
        }
#pragma unroll
        for (int i = 0; i < 2; i++) {
            int row0 = n0 + wy * 32 + i * 16;
            if (row0 + 16 <= N_NODES_C) {
#pragma unroll
                for (int j = 0; j < 4; j++)
                    wmma::store_matrix_sync(&g_Y[(size_t)row0 * 256 + wx * 64 + j * 16],
                                            acc[i][j], 256, wmma::mem_row_major);
            }
        }
    }
}

// ================= stats pass: warp-per-node over CSR, 2-edge ILP =====================
__global__ void __launch_bounds__(256)
k_stats(const float* __restrict__ xin, const float* __restrict__ W1c) {
    __shared__ float w1c[6 * 128];
    __shared__ float red[2 * 128];

    int tid = threadIdx.x;
    int warp = tid >> 5, lane = tid & 31;
    for (int i = tid; i < 6 * 128; i += 256) w1c[i] = W1c[i];
    if (tid < 256) red[tid] = 0.f;
    __syncthreads();

    float acc_s[4] = {0.f, 0.f, 0.f, 0.f};
    float acc_q[4] = {0.f, 0.f, 0.f, 0.f};
    int col = lane * 4;
    float sgn0 = (lane == 0) ? 1.f : -1.f;

    int gw = blockIdx.x * 8 + warp;
    int tw = gridDim.x * 8;
    for (int n = gw; n < N_NODES_C; n += tw) {
        float4 xr = *(const float4*)&xin[(size_t)n * NH + col];
        float4 y1 = *(const float4*)&g_Y[(size_t)n * 256 + col];
        float hb[4] = {y1.x, y1.y, y1.z, y1.w};
        int beg = g_rowptr[n], end = g_rowptr[n + 1];
        int j = beg;

        // 2 edges per iteration: interleaved gathers + shuffle chains
        for (; j + 1 < end; j += 2) {
            int c0 = g_colj[j];
            int c1 = g_colj[j + 1];
            float4 xc0 = *(const float4*)&xin[(size_t)c0 * NH + col];
            float4 xc1 = *(const float4*)&xin[(size_t)c1 * NH + col];
            float4 y20 = *(const float4*)&g_Y[(size_t)c0 * 256 + 128 + col];
            float4 y21 = *(const float4*)&g_Y[(size_t)c1 * 256 + 128 + col];
            float4 ev0 = *(const float4*)&g_eap[(size_t)j * 4];
            float4 ev1 = *(const float4*)&g_eap[(size_t)(j + 1) * 4];

            float d0x = xr.x - xc0.x, d0y = xr.y - xc0.y, d0z = xr.z - xc0.z, d0w = xr.w - xc0.w;
            float d1x = xr.x - xc1.x, d1y = xr.y - xc1.y, d1z = xr.z - xc1.z, d1w = xr.w - xc1.w;
            float dd0 = sgn0 * d0x * d0x - d0y * d0y - d0z * d0z - d0w * d0w;
            float ij0 = sgn0 * xr.x * xc0.x - xr.y * xc0.y - xr.z * xc0.z - xr.w * xc0.w;
            float dd1 = sgn0 * d1x * d1x - d1y * d1y - d1z * d1z - d1w * d1w;
            float ij1 = sgn0 * xr.x * xc1.x - xr.y * xc1.y - xr.z * xc1.z - xr.w * xc1.w;
#pragma unroll
            for (int o = 16; o; o >>= 1) {
                dd0 += __shfl_xor_sync(0xffffffffu, dd0, o);
                ij0 += __shfl_xor_sync(0xffffffffu, ij0, o);
                dd1 += __shfl_xor_sync(0xffffffffu, dd1, o);
                ij1 += __shfl_xor_sync(0xffffffffu, ij1, o);
            }
            float nrm0 = psi_f(dd0), dt0 = psi_f(ij0);
            float nrm1 = psi_f(dd1), dt1 = psi_f(ij1);

            float hv0[4] = {hb[0] + y20.x, hb[1] + y20.y, hb[2] + y20.z, hb[3] + y20.w};
            float hv1[4] = {hb[0] + y21.x, hb[1] + y21.y, hb[2] + y21.z, hb[3] + y21.w};
            float ho0[4], ho1[4];
#pragma unroll
            for (int q = 0; q < 4; q++) {
                int cc = col + q;
                float w0 = w1c[cc], w1 = w1c[128 + cc], w2 = w1c[256 + cc];
                float w3 = w1c[384 + cc], w4 = w1c[512 + cc], w5 = w1c[640 + cc];
                float h0 = hv0[q], h1 = hv1[q];
                h0 = fmaf(ev0.x, w0, h0);  h1 = fmaf(ev1.x, w0, h1);
                h0 = fmaf(ev0.y, w1, h0);  h1 = fmaf(ev1.y, w1, h1);
                h0 = fmaf(ev0.z, w2, h0);  h1 = fmaf(ev1.z, w2, h1);
                h0 = fmaf(ev0.w, w3, h0);  h1 = fmaf(ev1.w, w3, h1);
                h0 = fmaf(nrm0, w4, h0);   h1 = fmaf(nrm1, w4, h1);
                h0 = fmaf(dt0, w5, h0);    h1 = fmaf(dt1, w5, h1);
                ho0[q] = h0; ho1[q] = h1;
                acc_s[q] += h0 + h1;
                acc_q[q] = fmaf(h0, h0, acc_q[q]);
                acc_q[q] = fmaf(h1, h1, acc_q[q]);
            }
            {
                __nv_bfloat162 a = __floats2bfloat162_rn(ho0[0], ho0[1]);
                __nv_bfloat162 b = __floats2bfloat162_rn(ho0[2], ho0[3]);
                uint2 pk; pk.x = *(unsigned int*)&a; pk.y = *(unsigned int*)&b;
                *(uint2*)&g_h[(size_t)j * NH + col] = pk;
            }
            {
                __nv_bfloat162 a = __floats2bfloat162_rn(ho1[0], ho1[1]);
                __nv_bfloat162 b = __floats2bfloat162_rn(ho1[2], ho1[3]);
                uint2 pk; pk.x = *(unsigned int*)&a; pk.y = *(unsigned int*)&b;
                *(uint2*)&g_h[(size_t)(j + 1) * NH + col] = pk;
            }
        }

        // tail edge
        if (j < end) {
            int c = g_colj[j];
            float4 xc = *(const float4*)&xin[(size_t)c * NH + col];
            float4 y2 = *(const float4*)&g_Y[(size_t)c * 256 + 128 + col];
            float dx = xr.x - xc.x, dy = xr.y - xc.y, dz = xr.z - xc.z, dw = xr.w - xc.w;
            float dd = sgn0 * dx * dx - dy * dy - dz * dz - dw * dw;
            float ij = sgn0 * xr.x * xc.x - xr.y * xc.y - xr.z * xc.z - xr.w * xc.w;
#pragma unroll
            for (int o = 16; o; o >>= 1) {
                dd += __shfl_xor_sync(0xffffffffu, dd, o);
                ij += __shfl_xor_sync(0xffffffffu, ij, o);
            }
            float nrm = psi_f(dd), dt = psi_f(ij);
            float4 eav = *(const float4*)&g_eap[(size_t)j * 4];
            float ho[4];
#pragma unroll
            for (int q = 0; q < 4; q++) {
                int cc = col + q;
                float h = hb[q] + ((const float*)&y2)[q];
                h = fmaf(eav.x, w1c[cc], h);
                h = fmaf(eav.y, w1c[128 + cc], h);
                h = fmaf(eav.z, w1c[256 + cc], h);
                h = fmaf(eav.w, w1c[384 + cc], h);
                h = fmaf(nrm, w1c[512 + cc], h);
                h = fmaf(dt, w1c[640 + cc], h);
                ho[q] = h;
                acc_s[q] += h;
                acc_q[q] = fmaf(h, h, acc_q[q]);
            }
            __nv_bfloat162 a = __floats2bfloat162_rn(ho[0], ho[1]);
            __nv_bfloat162 b = __floats2bfloat162_rn(ho[2], ho[3]);
            uint2 pk; pk.x = *(unsigned int*)&a; pk.y = *(unsigned int*)&b;
            *(uint2*)&g_h[(size_t)j * NH + col] = pk;
        }
    }
#pragma unroll
    for (int q = 0; q < 4; q++) {
        atomicAdd(&red[col + q], acc_s[q]);
        atomicAdd(&red[128 + col + q], acc_q[q]);
    }
    __syncthreads();
    if (tid < 256) atomicAdd(&g_stats[tid], red[tid]);
}

// ================= fused edge MLP: FOUR 4-warp pipelines, in-CTA BN finalize ==========
#define BARG() asm volatile("bar.sync %0, 128;" :: "r"(group + 1) : "memory")

__global__ void __launch_bounds__(512, 1)
k_fused(const float* __restrict__ gamma, const float* __restrict__ beta,
        const float* __restrict__ W2, const float* __restrict__ b2,
        const float* __restrict__ Wa, const float* __restrict__ ba,
        const float* __restrict__ Wb,
        const float* __restrict__ Wm, const float* __restrict__ bm) {
    extern __shared__ __align__(16) char smraw[];
    __nv_bfloat16* W2s = (__nv_bfloat16*)smraw;       // 128 x 136
    __nv_bfloat16* Was = W2s + 128 * 136;             // 128 x 136
    __nv_bfloat16* Sall = Was + 128 * 136;            // 4 x (32 x 136) bf16
    float* Sfall = (float*)(Sall + 4 * 32 * 136);     // 4 x (32 x 132) fp32
    float* p_bnA = Sfall + 4 * 32 * 132;
    float* p_bnB = p_bnA + NH;
    float* p_b2  = p_bnB + NH;
    float* p_ba  = p_b2 + NH;
    float* p_Wm  = p_ba + NH;
    float* p_Wb  = p_Wm + NH;
    float* wg_all = p_Wb + NH;                        // 4 x 32

    int tid = threadIdx.x;
    int warp = tid >> 5, lane = tid & 31;
    int group = warp >> 2;                 // 0..3
    int gwarp = warp & 3;                  // 0..3 (column quarter)
    float bmv = bm[0];

    __nv_bfloat16* S  = Sall + group * 32 * 136;
    float*         Sf = Sfall + group * 32 * 132;
    float*         wgv = wg_all + group * 32;

    for (int idx = tid; idx < NH * NH; idx += 512) {
        int k = idx >> 7, c = idx & 127;
        W2s[k * 136 + c] = bf(W2[idx]);
        Was[k * 136 + c] = bf(Wa[idx]);
    }
    if (tid < NH) {
        float inv = 1.f / (float)N_EDGES_C;
        float mean = g_stats[tid] * inv;
        float var = g_stats[NH + tid] * inv - mean * mean;
        float sc = gamma[tid] * rsqrtf(var + BN_EPS);
        p_bnA[tid] = sc;
        p_bnB[tid] = beta[tid] - mean * sc;
        p_b2[tid]  = b2[tid];
        p_ba[tid]  = ba[tid];
        p_Wm[tid]  = Wm[tid];
        p_Wb[tid]  = Wb[tid];
    }
    __syncthreads();

    const int NT = N_EDGES_C / 32;          // 10000
    int tid_g = tid & 127;
    int pe = tid_g >> 4, pg = tid_g & 15;

    int tile = blockIdx.x * 4 + group;
    uint4 pre[4];
    if (tile < NT) {
#pragma unroll
        for (int it = 0; it < 4; it++) {
            int e = pe + it * 8;
            pre[it] = *(const uint4*)&g_h[(size_t)(tile * 32 + e) * NH + pg * 8];
        }
    }

    for (; tile < NT; tile += GRID_P * 4) {
        int e0 = tile * 32;

        // phase 1: convert prefetched hpre; BN + ReLU -> S
#pragma unroll
        for (int it = 0; it < 4; it++) {
            int e = pe + it * 8;
            __nv_bfloat162* hp = (__nv_bfloat162*)&pre[it];
            int cc0 = pg * 8;
            uint4 outp;
            __nv_bfloat162* op = (__nv_bfloat162*)&outp;
#pragma unroll
            for (int q = 0; q < 4; q++) {
                float2 f = __bfloat1622float2(hp[q]);
                int c0 = cc0 + q * 2;
                float v0 = fmaxf(fmaf(f.x, p_bnA[c0 + 0], p_bnB[c0 + 0]), 0.f);
                float v1 = fmaxf(fmaf(f.y, p_bnA[c0 + 1], p_bnB[c0 + 1]), 0.f);
                op[q] = __floats2bfloat162_rn(v0, v1);
            }
            *(uint4*)&S[e * 136 + pg * 8] = outp;
        }
        {
            int ntile = tile + GRID_P * 4;
            if (ntile < NT) {
#pragma unroll
                for (int it = 0; it < 4; it++) {
                    int e = pe + it * 8;
                    pre[it] = *(const uint4*)&g_h[(size_t)(ntile * 32 + e) * NH + pg * 8];
                }
            }
        }
        BARG();

        // phase 2: Sf = S @ W2
        {
            FragC acc[2][2];
#pragma unroll
            for (int i = 0; i < 2; i++)
#pragma unroll
                for (int j = 0; j < 2; j++) wmma::fill_fragment(acc[i][j], 0.f);
#pragma unroll
            for (int kk = 0; kk < NH; kk += 16) {
                FragA a0, a1; FragB b0, b1;
                wmma::load_matrix_sync(a0, &S[0 * 136 + kk], 136);
                wmma::load_matrix_sync(a1, &S[16 * 136 + kk], 136);
                wmma::load_matrix_sync(b0, &W2s[kk * 136 + gwarp * 32], 136);
                wmma::load_matrix_sync(b1, &W2s[kk * 136 + gwarp * 32 + 16], 136);
                wmma::mma_sync(acc[0][0], a0, b0, acc[0][0]);
                wmma::mma_sync(acc[0][1], a0, b1, acc[0][1]);
                wmma::mma_sync(acc[1][0], a1, b0, acc[1][0]);
                wmma::mma_sync(acc[1][1], a1, b1, acc[1][1]);
            }
#pragma unroll
            for (int i = 0; i < 2; i++)
#pragma unroll
                for (int j = 0; j < 2; j++)
                    wmma::store_matrix_sync(&Sf[(i * 16) * 132 + gwarp * 32 + j * 16],
                                            acc[i][j], 132, wmma::mem_row_major);
        }
        BARG();

        // phase 3: bias + ReLU -> S; gate -> wgv
#pragma unroll
        for (int t = 0; t < 8; t++) {
            int e = gwarp * 8 + t;
            float v[4];
            float p = 0.f;
#pragma unroll
            for (int u = 0; u < 4; u++) {
                int c = lane + 32 * u;
                v[u] = fmaxf(Sf[e * 132 + c] + p_b2[c], 0.f);
                p = fmaf(v[u], p_Wm[c], p);
            }
#pragma unroll
            for (int o = 16; o; o >>= 1) p += __shfl_xor_sync(0xffffffffu, p, o);
            if (lane == 0) wgv[e] = sigmoid_f(p + bmv);
#pragma unroll
            for (int u = 0; u < 4; u++) {
                int c = lane + 32 * u;
                S[e * 136 + c] = bf(v[u]);
            }
        }
        BARG();

        // phase 4: Sf = S @ Wa
        {
            FragC acc[2][2];
#pragma unroll
            for (int i = 0; i < 2; i++)
#pragma unroll
                for (int j = 0; j < 2; j++) wmma::fill_fragment(acc[i][j], 0.f);
#pragma unroll
            for (int kk = 0; kk < NH; kk += 16) {
                FragA a0, a1; FragB b0, b1;
                wmma::load_matrix_sync(a0, &S[0 * 136 + kk], 136);
                wmma::load_matrix_sync(a1, &S[16 * 136 + kk], 136);
                wmma::load_matrix_sync(b0, &Was[kk * 136 + gwarp * 32], 136);
                wmma::load_matrix_sync(b1, &Was[kk * 136 + gwarp * 32 + 16], 136);
                wmma::mma_sync(acc[0][0], a0, b0, acc[0][0]);
                wmma::mma_sync(acc[0][1], a0, b1, acc[0][1]);
                wmma::mma_sync(acc[1][0], a1, b0, acc[1][0]);
                wmma::mma_sync(acc[1][1], a1, b1, acc[1][1]);
            }
#pragma unroll
            for (int i = 0; i < 2; i++)
#pragma unroll
                for (int j = 0; j < 2; j++)
                    wmma::store_matrix_sync(&Sf[(i * 16) * 132 + gwarp * 32 + j * 16],
                                            acc[i][j], 132, wmma::mem_row_major);
        }
        BARG();

        // phase 5: s = ReLU(wg * Sf + ba) . Wb -> g_s (no trailing barrier)
#pragma unroll
        for (int t = 0; t < 8; t++) {
            int e = gwarp * 8 + t;
            float wg = wgv[e];
            float p = 0.f;
#pragma unroll
            for (int u = 0; u < 4; u++) {
                int c = lane + 32 * u;
                p = fmaf(fmaxf(fmaf(wg, Sf[e * 132 + c], p_ba[c]), 0.f), p_Wb[c], p);
            }
#pragma unroll
            for (int o = 16; o; o >>= 1) p += __shfl_xor_sync(0xffffffffu, p, o);
            if (lane == 0) g_s[e0 + e] = p;
        }
    }
}

// ================= aggregation (slot order, 2-edge ILP; fused head; resets stats) =====
__global__ void __launch_bounds__(256)
k_agg(const float* __restrict__ xin, float* __restrict__ xout,
      int is_final,
      const float* __restrict__ We, const float* __restrict__ be,
      float* __restrict__ out) {
    if (blockIdx.x == 0 && threadIdx.x < 2 * NH) g_stats[threadIdx.x] = 0.f;
    int n = blockIdx.x * 8 + (threadIdx.x >> 5);
    if (n >= N_NODES_C) return;
    int lane = threadIdx.x & 31;
    float4 xi = *(const float4*)&xin[(size_t)n * NH + lane * 4];
    float4 acc = xi;
    int beg = g_rowptr[n], end = g_rowptr[n + 1];
    int j = beg;
    for (; j + 1 < end; j += 2) {
        float s0 = g_s[j], s1 = g_s[j + 1];
        int c0 = g_colj[j], c1 = g_colj[j + 1];
        float4 xc0 = *(const float4*)&xin[(size_t)c0 * NH + lane * 4];
        float4 xc1 = *(const float4*)&xin[(size_t)c1 * NH + lane * 4];
        acc.x += fminf(fmaxf((xi.x - xc0.x) * s0, -100.f), 100.f)
               + fminf(fmaxf((xi.x - xc1.x) * s1, -100.f), 100.f);
        acc.y += fminf(fmaxf((xi.y - xc0.y) * s0, -100.f), 100.f)
               + fminf(fmaxf((xi.y - xc1.y) * s1, -100.f), 100.f);
        acc.z += fminf(fmaxf((xi.z - xc0.z) * s0, -100.f), 100.f)
               + fminf(fmaxf((xi.z - xc1.z) * s1, -100.f), 100.f);
        acc.w += fminf(fmaxf((xi.w - xc0.w) * s0, -100.f), 100.f)
               + fminf(fmaxf((xi.w - xc1.w) * s1, -100.f), 100.f);
    }
    if (j < end) {
        float s = g_s[j];
        int c = g_colj[j];
        float4 xc = *(const float4*)&xin[(size_t)c * NH + lane * 4];
        acc.x += fminf(fmaxf((xi.x - xc.x) * s, -100.f), 100.f);
        acc.y += fminf(fmaxf((xi.y - xc.y) * s, -100.f), 100.f);
        acc.z += fminf(fmaxf((xi.z - xc.z) * s, -100.f), 100.f);
        acc.w += fminf(fmaxf((xi.w - xc.w) * s, -100.f), 100.f);
    }
    if (is_final) {
        int k0 = lane * 4;
        float p0 = acc.x * We[k0 * 2] + acc.y * We[(k0 + 1) * 2]
                 + acc.z * We[(k0 + 2) * 2] + acc.w * We[(k0 + 3) * 2];
        float p1 = acc.x * We[k0 * 2 + 1] + acc.y * We[(k0 + 1) * 2 + 1]
                 + acc.z * We[(k0 + 2) * 2 + 1] + acc.w * We[(k0 + 3) * 2 + 1];
#pragma unroll
        for (int o = 16; o; o >>= 1) {
            p0 += __shfl_xor_sync(0xffffffffu, p0, o);
            p1 += __shfl_xor_sync(0xffffffffu, p1, o);
        }
        if (lane == 0) {
            out[(size_t)n * 2 + 0] = sigmoid_f(p0 + be[0]);
            out[(size_t)n * 2 + 1] = sigmoid_f(p1 + be[1]);
        }
    } else {
        *(float4*)&xout[(size_t)n * NH + lane * 4] = acc;
    }
}

// ================= launch ==============================================================
extern "C" void kernel_launch(void* const* d_in, const int* in_sizes, int n_in,
                              void* d_out, int out_size) {
    (void)in_sizes; (void)n_in; (void)out_size;
    const float* x     = (const float*)d_in[0];
    const int*   ei    = (const int*)d_in[1];
    const float* ea    = (const float*)d_in[2];
    const float* W1    = (const float*)d_in[3];
    const float* gamma = (const float*)d_in[4];
    const float* beta  = (const float*)d_in[5];
    const float* W2    = (const float*)d_in[6];
    const float* b2    = (const float*)d_in[7];
    const float* Wa    = (const float*)d_in[8];
    const float* ba    = (const float*)d_in[9];
    const float* Wb    = (const float*)d_in[10];
    const float* Wm    = (const float*)d_in[11];
    const float* bm    = (const float*)d_in[12];
    const float* We    = (const float*)d_in[13];
    const float* be    = (const float*)d_in[14];
    float* out = (float*)d_out;

    const int smem_node  = 128 * 264 * 2 + 64 * 136 * 2;
    const int smem_fused = 2 * 128 * 136 * 2
                         + 4 * 32 * 136 * 2
                         + 4 * 32 * 132 * 4
                         + (6 * 128 + 128) * 4;
    cudaFuncSetAttribute(k_node,  cudaFuncAttributeMaxDynamicSharedMemorySize, smem_node);
    cudaFuncSetAttribute(k_fused, cudaFuncAttributeMaxDynamicSharedMemorySize, smem_fused);

    void *px = nullptr, *pcnt = nullptr, *pstats = nullptr, *px2 = nullptr;
    cudaGetSymbolAddress(&px, g_x);
    cudaGetSymbolAddress(&px2, g_x2);
    cudaGetSymbolAddress(&pcnt, g_cnt);
    cudaGetSymbolAddress(&pstats, g_stats);

    cudaMemcpyAsync(px, x, sizeof(float) * N_NODES_C * NH, cudaMemcpyDeviceToDevice, 0);
    cudaMemsetAsync(pcnt, 0, N_NODES_C * sizeof(int), 0);
    cudaMemsetAsync(pstats, 0, 2 * NH * sizeof(float), 0);

    k_hist<<<(N_EDGES_C + 255) / 256, 256>>>(ei);
    k_scan<<<1, 1024>>>();
    k_fillcsr<<<(N_EDGES_C + 255) / 256, 256>>>(ei);
    k_sortseg<<<(N_NODES_C + 255) / 256, 256>>>();
    k_perm<<<(N_EDGES_C + 255) / 256, 256>>>(ei, ea);

    float* bufA = (float*)px;
    float* bufB = (float*)px2;

    for (int l = 0; l < NLAYERS; l++) {
        const float* W1l = W1 + (size_t)l * DIN * NH;
        const float* xin  = (l & 1) ? bufB : bufA;
        float*       xout = (l & 1) ? bufA : bufB;
        int is_final = (l == NLAYERS - 1);
        k_node<<<GRID_P * 2, 256, smem_node>>>(xin, W1l);
        k_stats<<<1184, 256>>>(xin, W1l + 256 * NH);
        k_fused<<<GRID_P, 512, smem_fused>>>(gamma + l * NH, beta + l * NH,
                                             W2 + (size_t)l * NH * NH, b2 + l * NH,
                                             Wa + (size_t)l * NH * NH, ba + l * NH,
                                             Wb + l * NH,
                                             Wm + l * NH, bm + l);
        k_agg<<<(N_NODES_C + 7) / 8, 256>>>(xin, xout, is_final, We, be, out);
    }
}